// round 9
// baseline (speedup 1.0000x reference)
#include <cuda_runtime.h>

// Problem constants
#define B_TOT 512
#define N_TOK 145
#define M_TOK 144
#define C_DIM 512
#define H_NUM 8
#define HD    64
#define NWIN  4
#define ROWS  (B_TOT * N_TOK)                   // 74240
#define QKV_ELEMS (B_TOT * H_NUM * N_TOK * HD)  // 38,010,880

// Scratch (device globals; no allocation allowed)
__device__ float g_q[QKV_ELEMS];
__device__ float g_k[QKV_ELEMS];
__device__ float g_v[QKV_ELEMS];
__device__ float g_opre[ROWS * C_DIM];
__device__ float g_xt[ROWS * C_DIM];            // tf32-rounded x
__device__ float g_wt[4][C_DIM * C_DIM];        // tf32-rounded Wq,Wk,Wv,Wo
__device__ float g_comb[NWIN * H_NUM][N_TOK * 152];  // mask+rpb, stride 152, -inf pad

__device__ __forceinline__ float tf32f(float x) {
    unsigned r;
    asm("cvt.rna.tf32.f32 %0, %1;" : "=r"(r) : "f"(x));
    return __uint_as_float(r);
}

// ---------------------------------------------------------------------------
// Pre-conversion kernels
// ---------------------------------------------------------------------------
__global__ void cvt_x_kernel(const float* __restrict__ x) {
    int i = blockIdx.x * 256 + threadIdx.x;
    float4 v = ((const float4*)x)[i];
    v.x = tf32f(v.x); v.y = tf32f(v.y); v.z = tf32f(v.z); v.w = tf32f(v.w);
    ((float4*)g_xt)[i] = v;
}

__global__ void cvt_w_kernel(const float* __restrict__ w0,
                             const float* __restrict__ w1,
                             const float* __restrict__ w2,
                             const float* __restrict__ w3) {
    const float* src = (blockIdx.y == 0) ? w0 : (blockIdx.y == 1) ? w1
                     : (blockIdx.y == 2) ? w2 : w3;
    int i = blockIdx.x * 256 + threadIdx.x;
    float4 v = ((const float4*)src)[i];
    v.x = tf32f(v.x); v.y = tf32f(v.y); v.z = tf32f(v.z); v.w = tf32f(v.w);
    ((float4*)g_wt[blockIdx.y])[i] = v;
}

// Fused mask + rpb, stride 152, cols >=145 filled with -1e30 (auto-mask)
__global__ void comb_kernel(const float* __restrict__ mask,
                            const float* __restrict__ rpb) {
    int i = blockIdx.x, wh = blockIdx.y;
    int w = wh >> 3, h = wh & 7;
    int j = threadIdx.x;
    if (j >= 152) return;
    float v;
    if (j < N_TOK) {
        v = mask[(size_t)w * N_TOK * N_TOK + i * N_TOK + j];
        if (i < M_TOK && j < M_TOK) {
            int iH = i / 12, iW = i - iH * 12;
            int jH = j / 12, jW = j - jH * 12;
            int idx = (iH - jH + 11) * 23 + (iW - jW + 11);
            v += rpb[idx * H_NUM + h];
        }
    } else {
        v = -1e30f;
    }
    g_comb[wh][i * 152 + j] = v;
}

// ---------------------------------------------------------------------------
// Common mma helpers
// ---------------------------------------------------------------------------
__device__ __forceinline__ void cpasync16(unsigned saddr, const void* g) {
    asm volatile("cp.async.cg.shared.global [%0], [%1], 16;"
                 :: "r"(saddr), "l"(g) : "memory");
}

__device__ __forceinline__ void ldsm4(unsigned* r, unsigned addr) {
    asm volatile("ldmatrix.sync.aligned.m8n8.x4.shared.b16 {%0,%1,%2,%3}, [%4];"
                 : "=r"(r[0]), "=r"(r[1]), "=r"(r[2]), "=r"(r[3]) : "r"(addr));
}

__device__ __forceinline__ void mma_tf32(float* d,
    unsigned a0, unsigned a1, unsigned a2, unsigned a3,
    unsigned b0, unsigned b1)
{
    asm volatile(
        "mma.sync.aligned.m16n8k8.row.col.f32.tf32.tf32.f32 "
        "{%0,%1,%2,%3}, {%4,%5,%6,%7}, {%8,%9}, {%0,%1,%2,%3};"
        : "+f"(d[0]), "+f"(d[1]), "+f"(d[2]), "+f"(d[3])
        : "r"(a0), "r"(a1), "r"(a2), "r"(a3), "r"(b0), "r"(b1));
}

// ---------------------------------------------------------------------------
// TF32 tensor-core NT GEMM, cp.async 5-stage pipeline + ldmatrix fragments.
// Block tile 128(m) x 256(n), 8 warps (2m x 4n) of 64x64, mma.m16n8k8.
// smem/stage: A 128x16 (2048 fl) + B 256x16 (4096 fl); word (row,k) at
//   row*16 + (((k>>2)^((row>>1)&3))<<2) + (k&3)   (verified conflict-free)
// ---------------------------------------------------------------------------
#define KC 16
#define NSTG (C_DIM / KC)   // 32
#define STAGES 5
#define STG_FLOATS 6144     // 2048 A + 4096 B
#define TGEMM_SMEM_BYTES (STAGES * STG_FLOATS * 4)   // 122880

__global__ void __launch_bounds__(256, 1) tgemm(
    const float* __restrict__ bias,
    float* __restrict__ outPlain,
    int sel)
{
    extern __shared__ float smd[];
    const float* A = (sel == 3) ? g_opre : g_xt;
    const float* W = g_wt[(sel == 3) ? 3 : sel];

    int tid = threadIdx.x;
    int lane = tid & 31, warp = tid >> 5;
    int wm = warp & 1, wn = warp >> 1;          // 2(m) x 4(n)
    int m0 = blockIdx.y * 128, n0 = blockIdx.x * 256;

    const float* Ag = A + (size_t)m0 * C_DIM;
    const float* Wg = W + (size_t)n0 * C_DIM;
    unsigned sbase = (unsigned)__cvta_generic_to_shared(smd);

    // cp.async mapping: 2 A-chunks + 4 B-chunks per thread per stage
    unsigned soA[2]; const float* gA[2];
#pragma unroll
    for (int i = 0; i < 2; i++) {
        int c = tid + i * 256;          // 512 A chunks
        int r = c >> 2, q = c & 3;
        soA[i] = (unsigned)(r * 16 + ((q ^ ((r >> 1) & 3)) << 2)) * 4u;
        gA[i] = Ag + (size_t)r * C_DIM + q * 4;
    }
    unsigned soB[4]; const float* gB[4];
#pragma unroll
    for (int i = 0; i < 4; i++) {
        int c = tid + i * 256;          // 1024 B chunks
        int r = c >> 2, q = c & 3;
        soB[i] = (unsigned)(r * 16 + ((q ^ ((r >> 1) & 3)) << 2)) * 4u;
        gB[i] = Wg + (size_t)r * C_DIM + q * 4;
    }

    // ldmatrix per-lane addressing
    int lr8 = lane & 7;
    int tq  = lane >> 3;
    unsigned aoff[4]; int akey[4];
#pragma unroll
    for (int mt = 0; mt < 4; mt++) {
        int arow = wm * 64 + mt * 16 + ((tq & 1) << 3) + lr8;
        aoff[mt] = (unsigned)(arow * 16);
        akey[mt] = (arow >> 1) & 3;
    }
    int akgh = tq >> 1;
    unsigned boff[4]; int bkey[4];
#pragma unroll
    for (int p = 0; p < 4; p++) {
        int brow = wn * 64 + p * 16 + ((lane >> 4) << 3) + lr8;
        boff[p] = (unsigned)(brow * 16);
        bkey[p] = (brow >> 1) & 3;
    }
    int bkgh = tq & 1;

    float acc[4][8][4];
#pragma unroll
    for (int mt = 0; mt < 4; mt++)
#pragma unroll
        for (int nt = 0; nt < 8; nt++)
#pragma unroll
            for (int i = 0; i < 4; i++) acc[mt][nt][i] = 0.f;

    // Prologue: stages 0..3
#pragma unroll
    for (int s = 0; s < 4; s++) {
        unsigned sb = sbase + (unsigned)(s * STG_FLOATS) * 4u;
        cpasync16(sb + soA[0], gA[0] + s * KC);
        cpasync16(sb + soA[1], gA[1] + s * KC);
#pragma unroll
        for (int i = 0; i < 4; i++)
            cpasync16(sb + 2048 * 4 + soB[i], gB[i] + s * KC);
        asm volatile("cp.async.commit_group;");
    }

    for (int s = 0; s < NSTG; s++) {
        if (s < NSTG - 3)       asm volatile("cp.async.wait_group 3;");
        else if (s == NSTG - 3) asm volatile("cp.async.wait_group 2;");
        else if (s == NSTG - 2) asm volatile("cp.async.wait_group 1;");
        else                    asm volatile("cp.async.wait_group 0;");
        __syncthreads();

        if (s + 4 < NSTG) {
            int sn = s + 4;
            unsigned sb = sbase + (unsigned)((sn % STAGES) * STG_FLOATS) * 4u;
            cpasync16(sb + soA[0], gA[0] + sn * KC);
            cpasync16(sb + soA[1], gA[1] + sn * KC);
#pragma unroll
            for (int i = 0; i < 4; i++)
                cpasync16(sb + 2048 * 4 + soB[i], gB[i] + sn * KC);
            asm volatile("cp.async.commit_group;");
        }

        unsigned stw = sbase + (unsigned)((s % STAGES) * STG_FLOATS) * 4u;
#pragma unroll
        for (int ks = 0; ks < 2; ks++) {
            unsigned af[4][4], bqf[4][4];
#pragma unroll
            for (int mt = 0; mt < 4; mt++) {
                int kg = 2 * ks + akgh;
                unsigned ad = stw + (aoff[mt] + (unsigned)((kg ^ akey[mt]) << 2)) * 4u;
                ldsm4(af[mt], ad);
            }
#pragma unroll
            for (int p = 0; p < 4; p++) {
                int kg = 2 * ks + bkgh;
                unsigned bd = stw + 2048 * 4u +
                              (boff[p] + (unsigned)((kg ^ bkey[p]) << 2)) * 4u;
                ldsm4(bqf[p], bd);
            }
#pragma unroll
            for (int mt = 0; mt < 4; mt++)
#pragma unroll
                for (int nt = 0; nt < 8; nt++) {
                    int p = nt >> 1, o = (nt & 1) * 2;
                    mma_tf32(acc[mt][nt], af[mt][0], af[mt][1], af[mt][2],
                             af[mt][3], bqf[p][o], bqf[p][o + 1]);
                }
        }
    }

    // Epilogue: bias add + scatter
    float* qkvbase = (sel == 0) ? g_q : (sel == 1) ? g_k : g_v;
    int cc = lane & 3, lrr = lane >> 2;
#pragma unroll
    for (int mt = 0; mt < 4; mt++) {
#pragma unroll
        for (int half = 0; half < 2; half++) {
            int gm = m0 + wm * 64 + mt * 16 + lrr + half * 8;
            int b_ = gm / N_TOK;
            int t  = gm - b_ * N_TOK;
#pragma unroll
            for (int nt = 0; nt < 8; nt++) {
                int gn = n0 + wn * 64 + nt * 8 + cc * 2;
                float v0 = acc[mt][nt][half * 2 + 0] + bias[gn];
                float v1 = acc[mt][nt][half * 2 + 1] + bias[gn + 1];
                float* dst;
                if (sel == 3) {
                    dst = outPlain + (size_t)gm * C_DIM + gn;
                } else {
                    int h = gn >> 6, d = gn & 63;
                    dst = qkvbase +
                          ((((size_t)b_ * H_NUM + h) * N_TOK + t) * HD + d);
                }
                *(float2*)dst = make_float2(v0, v1);
            }
        }
    }
}

// ---------------------------------------------------------------------------
// Tensor-core window attention (as R8) with vectorized staging.
// One block per (b_,h), 288 threads = 9 warps; warp w owns rows [16w,16w+16).
// ---------------------------------------------------------------------------
#define AT_SMEM_BYTES ((160 * 64 + 64 * 160) * 4)   // 81920

__global__ void __launch_bounds__(288, 1) attn_kernel()
{
    extern __shared__ __align__(16) float sm[];
    float* Ks = sm;              // 160 x 64
    float* Vt = sm + 160 * 64;   // 64 x 160

    int bh = blockIdx.x;
    int b_ = bh >> 3, h = bh & 7, w = b_ & 3;
    const float* gK = g_k + (size_t)bh * (N_TOK * HD);
    const float* gV = g_v + (size_t)bh * (N_TOK * HD);
    const float* gQ = g_q + (size_t)bh * (N_TOK * HD);
    const float* comb = g_comb[w * 8 + h];
    int tid = threadIdx.x, lane = tid & 31, warp = tid / 32;

    // Stage K [n][k]: swizzle permutes whole 4-word groups -> float4 LDG+STS
    for (int i4 = tid; i4 < 160 * 16; i4 += 288) {
        int n = i4 >> 4, g = i4 & 15;
        float4 v = (n < N_TOK) ? ((const float4*)gK)[n * 16 + g]
                               : make_float4(0.f, 0.f, 0.f, 0.f);
        v.x = tf32f(v.x); v.y = tf32f(v.y); v.z = tf32f(v.z); v.w = tf32f(v.w);
        int off = n * 64 + (((g & 8) | ((g & 7) ^ (n & 7))) << 2);
        *(float4*)(Ks + off) = v;
    }
    // Stage V transposed [d][n]: float4 LDG (coalesced) + 4 scalar STS
    for (int i4 = tid; i4 < 160 * 16; i4 += 288) {
        int n = i4 >> 4, dg = i4 & 15;
        float4 v = (n < N_TOK) ? ((const float4*)gV)[n * 16 + dg]
                               : make_float4(0.f, 0.f, 0.f, 0.f);
        int g = n >> 2, n3 = n & 3;
        const float* vf = &v.x;
#pragma unroll
        for (int j = 0; j < 4; j++) {
            int d = 4 * dg + j;
            int off = d * 160 + ((((g & ~7) | ((g & 7) ^ (d & 7)))) << 2) + n3;
            Vt[off] = tf32f(vf[j]);
        }
    }

    int c = lane & 3, lr = lane >> 2;
    int m0 = warp * 16;

    // Q in registers, A-fragment layout, tf32-rounded
    float aq[8][4];
    {
        const float* q0 = gQ + (m0 + lr) * 64;
        const float* q1 = gQ + (m0 + lr + 8) * 64;
#pragma unroll
        for (int ks = 0; ks < 8; ks++) {
            aq[ks][0] = tf32f(q0[8 * ks + c]);
            aq[ks][1] = tf32f(q1[8 * ks + c]);
            aq[ks][2] = tf32f(q0[8 * ks + c + 4]);
            aq[ks][3] = tf32f(q1[8 * ks + c + 4]);
        }
    }
    __syncthreads();

    // ldmatrix lane geometry
    int rowLocal = ((lane >> 4) << 3) + (lane & 7);
    int kbit = (lane >> 3) & 1;
    int rk7 = rowLocal & 7;

    unsigned ksBase = (unsigned)__cvta_generic_to_shared(Ks);
    unsigned vtBase = (unsigned)__cvta_generic_to_shared(Vt);

    float sacc[19][4];
#pragma unroll
    for (int t = 0; t < 19; t++)
#pragma unroll
        for (int i = 0; i < 4; i++) sacc[t][i] = 0.f;

    // ---- S = Q K^T ----
#pragma unroll
    for (int ks = 0; ks < 8; ks++) {
        int kg = 2 * ks + kbit;
        unsigned sw = (unsigned)(((kg & 8) | ((kg & 7) ^ rk7)) << 2);
        unsigned a0 = __float_as_uint(aq[ks][0]);
        unsigned a1 = __float_as_uint(aq[ks][1]);
        unsigned a2 = __float_as_uint(aq[ks][2]);
        unsigned a3 = __float_as_uint(aq[ks][3]);
#pragma unroll
        for (int tp = 0; tp < 10; tp++) {
            unsigned addr = ksBase +
                ((unsigned)((16 * tp + rowLocal) * 64) + sw) * 4u;
            unsigned br[4];
            ldsm4(br, addr);
            mma_tf32(sacc[2 * tp], a0, a1, a2, a3, br[0], br[1]);
            if (2 * tp + 1 < 19)
                mma_tf32(sacc[2 * tp + 1], a0, a1, a2, a3, br[2], br[3]);
        }
    }

    // ---- softmax in registers ----
    const float* crow0 = comb + (m0 + lr) * 152 + 2 * c;
    const float* crow1 = comb + (m0 + lr + 8) * 152 + 2 * c;
    float mx0 = -1e30f, mx1 = -1e30f;
#pragma unroll
    for (int t = 0; t < 19; t++) {
        float2 cb0 = *(const float2*)(crow0 + 8 * t);
        float2 cb1 = *(const float2*)(crow1 + 8 * t);
        sacc[t][0] = sacc[t][0] * 0.125f + cb0.x;
        sacc[t][1] = sacc[t][1] * 0.125f + cb0.y;
        sacc[t][2] = sacc[t][2] * 0.125f + cb1.x;
        sacc[t][3] = sacc[t][3] * 0.125f + cb1.y;
        mx0 = fmaxf(mx0, fmaxf(sacc[t][0], sacc[t][1]));
        mx1 = fmaxf(mx1, fmaxf(sacc[t][2], sacc[t][3]));
    }
    mx0 = fmaxf(mx0, __shfl_xor_sync(0xffffffffu, mx0, 1));
    mx0 = fmaxf(mx0, __shfl_xor_sync(0xffffffffu, mx0, 2));
    mx1 = fmaxf(mx1, __shfl_xor_sync(0xffffffffu, mx1, 1));
    mx1 = fmaxf(mx1, __shfl_xor_sync(0xffffffffu, mx1, 2));

    float l0 = 0.f, l1 = 0.f;
#pragma unroll
    for (int t = 0; t < 19; t++) {
        float p0 = __expf(sacc[t][0] - mx0);
        float p1 = __expf(sacc[t][1] - mx0);
        float p2 = __expf(sacc[t][2] - mx1);
        float p3 = __expf(sacc[t][3] - mx1);
        l0 += p0 + p1;
        l1 += p2 + p3;
        sacc[t][0] = tf32f(p0);
        sacc[t][1] = tf32f(p1);
        sacc[t][2] = tf32f(p2);
        sacc[t][3] = tf32f(p3);
    }
    l0 += __shfl_xor_sync(0xffffffffu, l0, 1);
    l0 += __shfl_xor_sync(0xffffffffu, l0, 2);
    l1 += __shfl_xor_sync(0xffffffffu, l1, 1);
    l1 += __shfl_xor_sync(0xffffffffu, l1, 2);

    // ---- O = P V ----
    float pacc[8][4];
#pragma unroll
    for (int dt = 0; dt < 8; dt++)
#pragma unroll
        for (int i = 0; i < 4; i++) pacc[dt][i] = 0.f;

    int src  = (lr << 2) + (c >> 1);
    int src2 = src + 2;
    bool odd = (c & 1) != 0;
#pragma unroll
    for (int kk = 0; kk < 19; kk++) {
        float s0 = __shfl_sync(0xffffffffu, sacc[kk][0], src);
        float s1 = __shfl_sync(0xffffffffu, sacc[kk][1], src);
        float s2 = __shfl_sync(0xffffffffu, sacc[kk][2], src);
        float s3 = __shfl_sync(0xffffffffu, sacc[kk][3], src);
        float t0 = __shfl_sync(0xffffffffu, sacc[kk][0], src2);
        float t1 = __shfl_sync(0xffffffffu, sacc[kk][1], src2);
        float t2 = __shfl_sync(0xffffffffu, sacc[kk][2], src2);
        float t3 = __shfl_sync(0xffffffffu, sacc[kk][3], src2);
        unsigned a0 = __float_as_uint(odd ? s1 : s0);
        unsigned a1 = __float_as_uint(odd ? s3 : s2);
        unsigned a2 = __float_as_uint(odd ? t1 : t0);
        unsigned a3 = __float_as_uint(odd ? t3 : t2);

        int kg = 2 * kk + kbit;
        unsigned sw = (unsigned)((((kg & ~7) | ((kg & 7) ^ rk7))) << 2);
#pragma unroll
        for (int p = 0; p < 4; p++) {
            unsigned addr = vtBase +
                ((unsigned)((16 * p + rowLocal) * 160) + sw) * 4u;
            unsigned br[4];
            ldsm4(br, addr);
            mma_tf32(pacc[2 * p],     a0, a1, a2, a3, br[0], br[1]);
            mma_tf32(pacc[2 * p + 1], a0, a1, a2, a3, br[2], br[3]);
        }
    }

    float inv0 = 1.f / l0, inv1 = 1.f / l1;
    float* dst0 = g_opre + (size_t)(b_ * N_TOK + m0 + lr) * C_DIM + h * HD;
    float* dst1 = dst0 + 8 * C_DIM;
#pragma unroll
    for (int dt = 0; dt < 8; dt++) {
        *(float2*)(dst0 + dt * 8 + 2 * c) =
            make_float2(tf32f(pacc[dt][0] * inv0), tf32f(pacc[dt][1] * inv0));
        *(float2*)(dst1 + dt * 8 + 2 * c) =
            make_float2(tf32f(pacc[dt][2] * inv1), tf32f(pacc[dt][3] * inv1));
    }
}

// ---------------------------------------------------------------------------
// Global-token redistribution: one block per (b, h).  (unchanged)
// ---------------------------------------------------------------------------
__global__ void __launch_bounds__(128) gx_kernel(const float* __restrict__ mask)
{
    __shared__ __align__(16) float L[580];
    __shared__ __align__(16) float Qg[256];
    __shared__ __align__(16) float red[128];
    __shared__ float s_inv;

    int b = blockIdx.x >> 3, h = blockIdx.x & 7;
    int tid = threadIdx.x;

    for (int i = tid; i < 256; i += 128) {
        int w = i >> 6, d = i & 63;
        Qg[i] = g_q[(((size_t)(b * 4 + w) * H_NUM + h) * N_TOK + M_TOK) * HD + d];
    }
    __syncthreads();

    for (int idx = tid; idx < 577; idx += 128) {
        if (idx < 576) {
            int w = idx / 144, n = idx - w * 144;
            const float4* kp = (const float4*)(g_k +
                (((size_t)(b * 4 + w) * H_NUM + h) * N_TOK + n) * HD);
            const float4* qp = (const float4*)(Qg + w * 64);
            float dot = 0.f;
#pragma unroll
            for (int t = 0; t < 16; t++) {
                float4 kv = kp[t], qv = qp[t];
                dot += kv.x * qv.x + kv.y * qv.y + kv.z * qv.z + kv.w * qv.w;
            }
            L[idx] = dot * 0.125f +
                     mask[(size_t)w * (N_TOK * N_TOK) + M_TOK * N_TOK + n];
        } else {
            float s = 0.f;
            for (int w = 0; w < 4; w++) {
                const float4* kp = (const float4*)(g_k +
                    (((size_t)(b * 4 + w) * H_NUM + h) * N_TOK + M_TOK) * HD);
                const float4* qp = (const float4*)(Qg + w * 64);
                float dot = 0.f;
#pragma unroll
                for (int t = 0; t < 16; t++) {
                    float4 kv = kp[t], qv = qp[t];
                    dot += kv.x * qv.x + kv.y * qv.y + kv.z * qv.z + kv.w * qv.w;
                }
                s += dot * 0.125f +
                     mask[(size_t)w * (N_TOK * N_TOK) + M_TOK * N_TOK + M_TOK];
            }
            L[576] = s * 0.25f;
        }
    }
    __syncthreads();

    float mx = -1e30f;
    for (int idx = tid; idx < 577; idx += 128) mx = fmaxf(mx, L[idx]);
    red[tid] = mx;
    __syncthreads();
    for (int s2 = 64; s2 > 0; s2 >>= 1) {
        if (tid < s2) red[tid] = fmaxf(red[tid], red[tid + s2]);
        __syncthreads();
    }
    mx = red[0];
    __syncthreads();

    float ps = 0.f;
    for (int idx = tid; idx < 577; idx += 128) {
        float e = __expf(L[idx] - mx);
        L[idx] = e;
        ps += e;
    }
    red[tid] = ps;
    __syncthreads();
    for (int s2 = 64; s2 > 0; s2 >>= 1) {
        if (tid < s2) red[tid] += red[tid + s2];
        __syncthreads();
    }
    if (tid == 0) s_inv = 1.f / red[0];
    __syncthreads();

    int d = tid & 63, half = tid >> 6;
    float acc = 0.f;
    for (int w = 0; w < 4; w++) {
        const float* vb = g_v + (((size_t)(b * 4 + w) * H_NUM + h) * N_TOK) * HD;
        for (int n = half; n < M_TOK; n += 2)
            acc += L[w * 144 + n] * vb[n * HD + d];
        if ((w & 1) == half)
            acc += L[576] * vb[M_TOK * HD + d];
    }
    red[tid] = acc;
    __syncthreads();
    if (half == 0) {
        float tot = tf32f((red[tid] + red[tid + 64]) * s_inv);
#pragma unroll
        for (int w = 0; w < 4; w++)
            g_opre[(size_t)((b * 4 + w) * N_TOK + M_TOK) * C_DIM + h * HD + d] = tot;
    }
}

// ---------------------------------------------------------------------------
extern "C" void kernel_launch(void* const* d_in, const int* in_sizes, int n_in,
                              void* d_out, int out_size)
{
    const float* x    = (const float*)d_in[0];
    const float* mask = (const float*)d_in[1];
    const float* rpb  = (const float*)d_in[2];
    const float* Wq   = (const float*)d_in[3];
    const float* bq   = (const float*)d_in[4];
    const float* Wk   = (const float*)d_in[5];
    const float* bk   = (const float*)d_in[6];
    const float* Wv   = (const float*)d_in[7];
    const float* bv   = (const float*)d_in[8];
    const float* Wo   = (const float*)d_in[9];
    const float* bo   = (const float*)d_in[10];
    float* out = (float*)d_out;

    cudaFuncSetAttribute(tgemm, cudaFuncAttributeMaxDynamicSharedMemorySize,
                         TGEMM_SMEM_BYTES);
    cudaFuncSetAttribute(attn_kernel, cudaFuncAttributeMaxDynamicSharedMemorySize,
                         AT_SMEM_BYTES);

    cvt_x_kernel<<<ROWS * C_DIM / 1024, 256>>>(x);
    cvt_w_kernel<<<dim3(C_DIM * C_DIM / 1024, 4), 256>>>(Wq, Wk, Wv, Wo);
    comb_kernel<<<dim3(N_TOK, NWIN * H_NUM), 160>>>(mask, rpb);

    dim3 gg(2, 580, 1);   // 512/256 x 74240/128
    tgemm<<<gg, 256, TGEMM_SMEM_BYTES>>>(bq, nullptr, 0);
    tgemm<<<gg, 256, TGEMM_SMEM_BYTES>>>(bk, nullptr, 1);
    tgemm<<<gg, 256, TGEMM_SMEM_BYTES>>>(bv, nullptr, 2);

    attn_kernel<<<4096, 288, AT_SMEM_BYTES>>>();
    gx_kernel<<<1024, 128>>>(mask);

    tgemm<<<gg, 256, TGEMM_SMEM_BYTES>>>(bo, out, 3);
}

// round 10
// speedup vs baseline: 1.1206x; 1.1206x over previous
#include <cuda_runtime.h>

// Problem constants
#define B_TOT 512
#define N_TOK 145
#define M_TOK 144
#define C_DIM 512
#define H_NUM 8
#define HD    64
#define NWIN  4
#define ROWS  (B_TOT * N_TOK)                   // 74240
#define QKV_ELEMS (B_TOT * H_NUM * N_TOK * HD)  // 38,010,880

// Scratch (device globals; no allocation allowed)
__device__ float g_q[QKV_ELEMS];
__device__ float g_k[QKV_ELEMS];
__device__ float g_v[QKV_ELEMS];
__device__ float g_opre[ROWS * C_DIM];
__device__ float g_xt[ROWS * C_DIM];            // tf32-rounded x
__device__ float g_wt[4][C_DIM * C_DIM];        // tf32-rounded Wq,Wk,Wv,Wo
__device__ float g_comb[NWIN * H_NUM][N_TOK * 152];  // mask+rpb, stride 152, -inf pad

__device__ __forceinline__ float tf32f(float x) {
    unsigned r;
    asm("cvt.rna.tf32.f32 %0, %1;" : "=r"(r) : "f"(x));
    return __uint_as_float(r);
}

// ---------------------------------------------------------------------------
// Pre-conversion kernels
// ---------------------------------------------------------------------------
__global__ void cvt_x_kernel(const float* __restrict__ x) {
    int i = blockIdx.x * 256 + threadIdx.x;
    float4 v = ((const float4*)x)[i];
    v.x = tf32f(v.x); v.y = tf32f(v.y); v.z = tf32f(v.z); v.w = tf32f(v.w);
    ((float4*)g_xt)[i] = v;
}

__global__ void cvt_w_kernel(const float* __restrict__ w0,
                             const float* __restrict__ w1,
                             const float* __restrict__ w2,
                             const float* __restrict__ w3) {
    const float* src = (blockIdx.y == 0) ? w0 : (blockIdx.y == 1) ? w1
                     : (blockIdx.y == 2) ? w2 : w3;
    int i = blockIdx.x * 256 + threadIdx.x;
    float4 v = ((const float4*)src)[i];
    v.x = tf32f(v.x); v.y = tf32f(v.y); v.z = tf32f(v.z); v.w = tf32f(v.w);
    ((float4*)g_wt[blockIdx.y])[i] = v;
}

// Fused mask + rpb, stride 152, cols >=145 filled with -1e30 (auto-mask)
__global__ void comb_kernel(const float* __restrict__ mask,
                            const float* __restrict__ rpb) {
    int i = blockIdx.x, wh = blockIdx.y;
    int w = wh >> 3, h = wh & 7;
    int j = threadIdx.x;
    if (j >= 152) return;
    float v;
    if (j < N_TOK) {
        v = mask[(size_t)w * N_TOK * N_TOK + i * N_TOK + j];
        if (i < M_TOK && j < M_TOK) {
            int iH = i / 12, iW = i - iH * 12;
            int jH = j / 12, jW = j - jH * 12;
            int idx = (iH - jH + 11) * 23 + (iW - jW + 11);
            v += rpb[idx * H_NUM + h];
        }
    } else {
        v = -1e30f;
    }
    g_comb[wh][i * 152 + j] = v;
}

// ---------------------------------------------------------------------------
// Common mma helpers
// ---------------------------------------------------------------------------
__device__ __forceinline__ void cpasync16(unsigned saddr, const void* g) {
    asm volatile("cp.async.cg.shared.global [%0], [%1], 16;"
                 :: "r"(saddr), "l"(g) : "memory");
}

__device__ __forceinline__ void ldsm4(unsigned* r, unsigned addr) {
    asm volatile("ldmatrix.sync.aligned.m8n8.x4.shared.b16 {%0,%1,%2,%3}, [%4];"
                 : "=r"(r[0]), "=r"(r[1]), "=r"(r[2]), "=r"(r[3]) : "r"(addr));
}

__device__ __forceinline__ void mma_tf32(float* d,
    unsigned a0, unsigned a1, unsigned a2, unsigned a3,
    unsigned b0, unsigned b1)
{
    asm volatile(
        "mma.sync.aligned.m16n8k8.row.col.f32.tf32.tf32.f32 "
        "{%0,%1,%2,%3}, {%4,%5,%6,%7}, {%8,%9}, {%0,%1,%2,%3};"
        : "+f"(d[0]), "+f"(d[1]), "+f"(d[2]), "+f"(d[3])
        : "r"(a0), "r"(a1), "r"(a2), "r"(a3), "r"(b0), "r"(b1));
}

// ---------------------------------------------------------------------------
// TF32 tensor-core NT GEMM, cp.async 5-stage pipeline + ldmatrix fragments.
// R8-proven config: block 128x128, 8 warps (2Mx4N), warp 64x32, 128 regs.
// qkv mode: gridDim.z = 3 (sel = blockIdx.z) computes Q,K,V in one launch.
// ---------------------------------------------------------------------------
#define KC 16
#define NSTG (C_DIM / KC)   // 32
#define STAGES 5
#define STG_FLOATS 4096     // 2048 A + 2048 B
#define TGEMM_SMEM_BYTES (STAGES * STG_FLOATS * 4)   // 81920

__global__ void __launch_bounds__(256, 2) tgemm(
    const float* __restrict__ biasQ,
    const float* __restrict__ biasK,
    const float* __restrict__ biasV,
    float* __restrict__ outPlain,
    int mode)   // 0: QKV (z selects), 3: final projection
{
    extern __shared__ float smd[];
    int sel = (mode == 3) ? 3 : (int)blockIdx.z;
    const float* A = (sel == 3) ? g_opre : g_xt;
    const float* W = g_wt[sel];
    const float* bias = (sel == 0) ? biasQ : (sel == 1) ? biasK
                      : (sel == 2) ? biasV : biasQ;  // mode3 passes bo as biasQ

    int tid = threadIdx.x;
    int lane = tid & 31, warp = tid >> 5;
    int wm = warp & 1, wn = warp >> 1;
    int m0 = blockIdx.y * 128, n0 = blockIdx.x * 128;

    const float* Ag = A + (size_t)m0 * C_DIM;
    const float* Wg = W + (size_t)n0 * C_DIM;
    unsigned sbase = (unsigned)__cvta_generic_to_shared(smd);

    int chk0 = tid, chk1 = tid + 256;
    int cm0 = chk0 >> 2, cc0 = chk0 & 3;
    int cm1 = chk1 >> 2, cc1 = chk1 & 3;
    unsigned so0 = (unsigned)(cm0 * 16 + ((cc0 ^ ((cm0 >> 1) & 3)) << 2)) * 4u;
    unsigned so1 = (unsigned)(cm1 * 16 + ((cc1 ^ ((cm1 >> 1) & 3)) << 2)) * 4u;
    const float* ag0 = Ag + (size_t)cm0 * C_DIM + cc0 * 4;
    const float* ag1 = Ag + (size_t)cm1 * C_DIM + cc1 * 4;
    const float* wg0 = Wg + (size_t)cm0 * C_DIM + cc0 * 4;
    const float* wg1 = Wg + (size_t)cm1 * C_DIM + cc1 * 4;

    int lr8 = lane & 7;
    int tq  = lane >> 3;
    unsigned aoff[4]; int akey[4];
#pragma unroll
    for (int mt = 0; mt < 4; mt++) {
        int arow = wm * 64 + mt * 16 + ((tq & 1) << 3) + lr8;
        aoff[mt] = (unsigned)(arow * 16);
        akey[mt] = (arow >> 1) & 3;
    }
    int akgh = tq >> 1;
    unsigned boff[2]; int bkey[2];
#pragma unroll
    for (int p = 0; p < 2; p++) {
        int brow = wn * 32 + p * 16 + ((lane >> 4) << 3) + lr8;
        boff[p] = (unsigned)(brow * 16);
        bkey[p] = (brow >> 1) & 3;
    }
    int bkgh = tq & 1;

    float acc[4][4][4];
#pragma unroll
    for (int mt = 0; mt < 4; mt++)
#pragma unroll
        for (int nt = 0; nt < 4; nt++)
#pragma unroll
            for (int i = 0; i < 4; i++) acc[mt][nt][i] = 0.f;

#pragma unroll
    for (int s = 0; s < 4; s++) {
        unsigned sb = sbase + (unsigned)(s * STG_FLOATS) * 4u;
        cpasync16(sb + so0, ag0 + s * KC);
        cpasync16(sb + so1, ag1 + s * KC);
        cpasync16(sb + 2048 * 4 + so0, wg0 + s * KC);
        cpasync16(sb + 2048 * 4 + so1, wg1 + s * KC);
        asm volatile("cp.async.commit_group;");
    }

    for (int s = 0; s < NSTG; s++) {
        if (s < NSTG - 3)       asm volatile("cp.async.wait_group 3;");
        else if (s == NSTG - 3) asm volatile("cp.async.wait_group 2;");
        else if (s == NSTG - 2) asm volatile("cp.async.wait_group 1;");
        else                    asm volatile("cp.async.wait_group 0;");
        __syncthreads();

        if (s + 4 < NSTG) {
            int sn = s + 4;
            unsigned sb = sbase + (unsigned)((sn % STAGES) * STG_FLOATS) * 4u;
            cpasync16(sb + so0, ag0 + sn * KC);
            cpasync16(sb + so1, ag1 + sn * KC);
            cpasync16(sb + 2048 * 4 + so0, wg0 + sn * KC);
            cpasync16(sb + 2048 * 4 + so1, wg1 + sn * KC);
            asm volatile("cp.async.commit_group;");
        }

        unsigned stw = sbase + (unsigned)((s % STAGES) * STG_FLOATS) * 4u;
#pragma unroll
        for (int ks = 0; ks < 2; ks++) {
            unsigned af[4][4], bq2[2][4];
#pragma unroll
            for (int mt = 0; mt < 4; mt++) {
                int kg = 2 * ks + akgh;
                unsigned ad = stw + (aoff[mt] + (unsigned)((kg ^ akey[mt]) << 2)) * 4u;
                ldsm4(af[mt], ad);
            }
#pragma unroll
            for (int p = 0; p < 2; p++) {
                int kg = 2 * ks + bkgh;
                unsigned bd = stw + 2048 * 4u +
                              (boff[p] + (unsigned)((kg ^ bkey[p]) << 2)) * 4u;
                ldsm4(bq2[p], bd);
            }
#pragma unroll
            for (int mt = 0; mt < 4; mt++)
#pragma unroll
                for (int nt = 0; nt < 4; nt++) {
                    int p = nt >> 1, o = (nt & 1) * 2;
                    mma_tf32(acc[mt][nt], af[mt][0], af[mt][1], af[mt][2],
                             af[mt][3], bq2[p][o], bq2[p][o + 1]);
                }
        }
    }

    float* qkvbase = (sel == 0) ? g_q : (sel == 1) ? g_k : g_v;
    int cc = lane & 3, lrr = lane >> 2;
#pragma unroll
    for (int mt = 0; mt < 4; mt++) {
#pragma unroll
        for (int half = 0; half < 2; half++) {
            int gm = m0 + wm * 64 + mt * 16 + lrr + half * 8;
            int b_ = gm / N_TOK;
            int t  = gm - b_ * N_TOK;
#pragma unroll
            for (int nt = 0; nt < 4; nt++) {
                int gn = n0 + wn * 32 + nt * 8 + cc * 2;
                float v0 = acc[mt][nt][half * 2 + 0] + bias[gn];
                float v1 = acc[mt][nt][half * 2 + 1] + bias[gn + 1];
                float* dst;
                if (sel == 3) {
                    dst = outPlain + (size_t)gm * C_DIM + gn;
                } else {
                    int h = gn >> 6, d = gn & 63;
                    dst = qkvbase +
                          ((((size_t)b_ * H_NUM + h) * N_TOK + t) * HD + d);
                }
                *(float2*)dst = make_float2(v0, v1);
            }
        }
    }
}

// ---------------------------------------------------------------------------
// Tensor-core window attention with vectorized staging (R9-proven).
// One block per (b_,h), 288 threads = 9 warps; warp w owns rows [16w,16w+16).
// ---------------------------------------------------------------------------
#define AT_SMEM_BYTES ((160 * 64 + 64 * 160) * 4)   // 81920

__global__ void __launch_bounds__(288, 1) attn_kernel()
{
    extern __shared__ __align__(16) float sm[];
    float* Ks = sm;              // 160 x 64
    float* Vt = sm + 160 * 64;   // 64 x 160

    int bh = blockIdx.x;
    int b_ = bh >> 3, h = bh & 7, w = b_ & 3;
    const float* gK = g_k + (size_t)bh * (N_TOK * HD);
    const float* gV = g_v + (size_t)bh * (N_TOK * HD);
    const float* gQ = g_q + (size_t)bh * (N_TOK * HD);
    const float* comb = g_comb[w * 8 + h];
    int tid = threadIdx.x, lane = tid & 31, warp = tid / 32;

    // Stage K [n][k]: swizzle permutes whole 4-word groups -> float4 LDG+STS
    for (int i4 = tid; i4 < 160 * 16; i4 += 288) {
        int n = i4 >> 4, g = i4 & 15;
        float4 v = (n < N_TOK) ? ((const float4*)gK)[n * 16 + g]
                               : make_float4(0.f, 0.f, 0.f, 0.f);
        v.x = tf32f(v.x); v.y = tf32f(v.y); v.z = tf32f(v.z); v.w = tf32f(v.w);
        int off = n * 64 + (((g & 8) | ((g & 7) ^ (n & 7))) << 2);
        *(float4*)(Ks + off) = v;
    }
    // Stage V transposed [d][n]: float4 LDG (coalesced) + 4 scalar STS
    for (int i4 = tid; i4 < 160 * 16; i4 += 288) {
        int n = i4 >> 4, dg = i4 & 15;
        float4 v = (n < N_TOK) ? ((const float4*)gV)[n * 16 + dg]
                               : make_float4(0.f, 0.f, 0.f, 0.f);
        int g = n >> 2, n3 = n & 3;
        const float* vf = &v.x;
#pragma unroll
        for (int j = 0; j < 4; j++) {
            int d = 4 * dg + j;
            int off = d * 160 + ((((g & ~7) | ((g & 7) ^ (d & 7)))) << 2) + n3;
            Vt[off] = tf32f(vf[j]);
        }
    }

    int c = lane & 3, lr = lane >> 2;
    int m0 = warp * 16;

    // Q in registers, A-fragment layout, tf32-rounded
    float aq[8][4];
    {
        const float* q0 = gQ + (m0 + lr) * 64;
        const float* q1 = gQ + (m0 + lr + 8) * 64;
#pragma unroll
        for (int ks = 0; ks < 8; ks++) {
            aq[ks][0] = tf32f(q0[8 * ks + c]);
            aq[ks][1] = tf32f(q1[8 * ks + c]);
            aq[ks][2] = tf32f(q0[8 * ks + c + 4]);
            aq[ks][3] = tf32f(q1[8 * ks + c + 4]);
        }
    }
    __syncthreads();

    // ldmatrix lane geometry
    int rowLocal = ((lane >> 4) << 3) + (lane & 7);
    int kbit = (lane >> 3) & 1;
    int rk7 = rowLocal & 7;

    unsigned ksBase = (unsigned)__cvta_generic_to_shared(Ks);
    unsigned vtBase = (unsigned)__cvta_generic_to_shared(Vt);

    float sacc[19][4];
#pragma unroll
    for (int t = 0; t < 19; t++)
#pragma unroll
        for (int i = 0; i < 4; i++) sacc[t][i] = 0.f;

    // ---- S = Q K^T ----
#pragma unroll
    for (int ks = 0; ks < 8; ks++) {
        int kg = 2 * ks + kbit;
        unsigned sw = (unsigned)(((kg & 8) | ((kg & 7) ^ rk7)) << 2);
        unsigned a0 = __float_as_uint(aq[ks][0]);
        unsigned a1 = __float_as_uint(aq[ks][1]);
        unsigned a2 = __float_as_uint(aq[ks][2]);
        unsigned a3 = __float_as_uint(aq[ks][3]);
#pragma unroll
        for (int tp = 0; tp < 10; tp++) {
            unsigned addr = ksBase +
                ((unsigned)((16 * tp + rowLocal) * 64) + sw) * 4u;
            unsigned br[4];
            ldsm4(br, addr);
            mma_tf32(sacc[2 * tp], a0, a1, a2, a3, br[0], br[1]);
            if (2 * tp + 1 < 19)
                mma_tf32(sacc[2 * tp + 1], a0, a1, a2, a3, br[2], br[3]);
        }
    }

    // ---- softmax in registers ----
    const float* crow0 = comb + (m0 + lr) * 152 + 2 * c;
    const float* crow1 = comb + (m0 + lr + 8) * 152 + 2 * c;
    float mx0 = -1e30f, mx1 = -1e30f;
#pragma unroll
    for (int t = 0; t < 19; t++) {
        float2 cb0 = *(const float2*)(crow0 + 8 * t);
        float2 cb1 = *(const float2*)(crow1 + 8 * t);
        sacc[t][0] = sacc[t][0] * 0.125f + cb0.x;
        sacc[t][1] = sacc[t][1] * 0.125f + cb0.y;
        sacc[t][2] = sacc[t][2] * 0.125f + cb1.x;
        sacc[t][3] = sacc[t][3] * 0.125f + cb1.y;
        mx0 = fmaxf(mx0, fmaxf(sacc[t][0], sacc[t][1]));
        mx1 = fmaxf(mx1, fmaxf(sacc[t][2], sacc[t][3]));
    }
    mx0 = fmaxf(mx0, __shfl_xor_sync(0xffffffffu, mx0, 1));
    mx0 = fmaxf(mx0, __shfl_xor_sync(0xffffffffu, mx0, 2));
    mx1 = fmaxf(mx1, __shfl_xor_sync(0xffffffffu, mx1, 1));
    mx1 = fmaxf(mx1, __shfl_xor_sync(0xffffffffu, mx1, 2));

    float l0 = 0.f, l1 = 0.f;
#pragma unroll
    for (int t = 0; t < 19; t++) {
        float p0 = __expf(sacc[t][0] - mx0);
        float p1 = __expf(sacc[t][1] - mx0);
        float p2 = __expf(sacc[t][2] - mx1);
        float p3 = __expf(sacc[t][3] - mx1);
        l0 += p0 + p1;
        l1 += p2 + p3;
        sacc[t][0] = tf32f(p0);
        sacc[t][1] = tf32f(p1);
        sacc[t][2] = tf32f(p2);
        sacc[t][3] = tf32f(p3);
    }
    l0 += __shfl_xor_sync(0xffffffffu, l0, 1);
    l0 += __shfl_xor_sync(0xffffffffu, l0, 2);
    l1 += __shfl_xor_sync(0xffffffffu, l1, 1);
    l1 += __shfl_xor_sync(0xffffffffu, l1, 2);

    // ---- O = P V ----
    float pacc[8][4];
#pragma unroll
    for (int dt = 0; dt < 8; dt++)
#pragma unroll
        for (int i = 0; i < 4; i++) pacc[dt][i] = 0.f;

    int src  = (lr << 2) + (c >> 1);
    int src2 = src + 2;
    bool odd = (c & 1) != 0;
#pragma unroll
    for (int kk = 0; kk < 19; kk++) {
        float s0 = __shfl_sync(0xffffffffu, sacc[kk][0], src);
        float s1 = __shfl_sync(0xffffffffu, sacc[kk][1], src);
        float s2 = __shfl_sync(0xffffffffu, sacc[kk][2], src);
        float s3 = __shfl_sync(0xffffffffu, sacc[kk][3], src);
        float t0 = __shfl_sync(0xffffffffu, sacc[kk][0], src2);
        float t1 = __shfl_sync(0xffffffffu, sacc[kk][1], src2);
        float t2 = __shfl_sync(0xffffffffu, sacc[kk][2], src2);
        float t3 = __shfl_sync(0xffffffffu, sacc[kk][3], src2);
        unsigned a0 = __float_as_uint(odd ? s1 : s0);
        unsigned a1 = __float_as_uint(odd ? s3 : s2);
        unsigned a2 = __float_as_uint(odd ? t1 : t0);
        unsigned a3 = __float_as_uint(odd ? t3 : t2);

        int kg = 2 * kk + kbit;
        unsigned sw = (unsigned)((((kg & ~7) | ((kg & 7) ^ rk7))) << 2);
#pragma unroll
        for (int p = 0; p < 4; p++) {
            unsigned addr = vtBase +
                ((unsigned)((16 * p + rowLocal) * 160) + sw) * 4u;
            unsigned br[4];
            ldsm4(br, addr);
            mma_tf32(pacc[2 * p],     a0, a1, a2, a3, br[0], br[1]);
            mma_tf32(pacc[2 * p + 1], a0, a1, a2, a3, br[2], br[3]);
        }
    }

    float inv0 = 1.f / l0, inv1 = 1.f / l1;
    float* dst0 = g_opre + (size_t)(b_ * N_TOK + m0 + lr) * C_DIM + h * HD;
    float* dst1 = dst0 + 8 * C_DIM;
#pragma unroll
    for (int dt = 0; dt < 8; dt++) {
        *(float2*)(dst0 + dt * 8 + 2 * c) =
            make_float2(tf32f(pacc[dt][0] * inv0), tf32f(pacc[dt][1] * inv0));
        *(float2*)(dst1 + dt * 8 + 2 * c) =
            make_float2(tf32f(pacc[dt][2] * inv1), tf32f(pacc[dt][3] * inv1));
    }
}

// ---------------------------------------------------------------------------
// Global-token redistribution: one block per (b, h).  (unchanged)
// ---------------------------------------------------------------------------
__global__ void __launch_bounds__(128) gx_kernel(const float* __restrict__ mask)
{
    __shared__ __align__(16) float L[580];
    __shared__ __align__(16) float Qg[256];
    __shared__ __align__(16) float red[128];
    __shared__ float s_inv;

    int b = blockIdx.x >> 3, h = blockIdx.x & 7;
    int tid = threadIdx.x;

    for (int i = tid; i < 256; i += 128) {
        int w = i >> 6, d = i & 63;
        Qg[i] = g_q[(((size_t)(b * 4 + w) * H_NUM + h) * N_TOK + M_TOK) * HD + d];
    }
    __syncthreads();

    for (int idx = tid; idx < 577; idx += 128) {
        if (idx < 576) {
            int w = idx / 144, n = idx - w * 144;
            const float4* kp = (const float4*)(g_k +
                (((size_t)(b * 4 + w) * H_NUM + h) * N_TOK + n) * HD);
            const float4* qp = (const float4*)(Qg + w * 64);
            float dot = 0.f;
#pragma unroll
            for (int t = 0; t < 16; t++) {
                float4 kv = kp[t], qv = qp[t];
                dot += kv.x * qv.x + kv.y * qv.y + kv.z * qv.z + kv.w * qv.w;
            }
            L[idx] = dot * 0.125f +
                     mask[(size_t)w * (N_TOK * N_TOK) + M_TOK * N_TOK + n];
        } else {
            float s = 0.f;
            for (int w = 0; w < 4; w++) {
                const float4* kp = (const float4*)(g_k +
                    (((size_t)(b * 4 + w) * H_NUM + h) * N_TOK + M_TOK) * HD);
                const float4* qp = (const float4*)(Qg + w * 64);
                float dot = 0.f;
#pragma unroll
                for (int t = 0; t < 16; t++) {
                    float4 kv = kp[t], qv = qp[t];
                    dot += kv.x * qv.x + kv.y * qv.y + kv.z * qv.z + kv.w * qv.w;
                }
                s += dot * 0.125f +
                     mask[(size_t)w * (N_TOK * N_TOK) + M_TOK * N_TOK + M_TOK];
            }
            L[576] = s * 0.25f;
        }
    }
    __syncthreads();

    float mx = -1e30f;
    for (int idx = tid; idx < 577; idx += 128) mx = fmaxf(mx, L[idx]);
    red[tid] = mx;
    __syncthreads();
    for (int s2 = 64; s2 > 0; s2 >>= 1) {
        if (tid < s2) red[tid] = fmaxf(red[tid], red[tid + s2]);
        __syncthreads();
    }
    mx = red[0];
    __syncthreads();

    float ps = 0.f;
    for (int idx = tid; idx < 577; idx += 128) {
        float e = __expf(L[idx] - mx);
        L[idx] = e;
        ps += e;
    }
    red[tid] = ps;
    __syncthreads();
    for (int s2 = 64; s2 > 0; s2 >>= 1) {
        if (tid < s2) red[tid] += red[tid + s2];
        __syncthreads();
    }
    if (tid == 0) s_inv = 1.f / red[0];
    __syncthreads();

    int d = tid & 63, half = tid >> 6;
    float acc = 0.f;
    for (int w = 0; w < 4; w++) {
        const float* vb = g_v + (((size_t)(b * 4 + w) * H_NUM + h) * N_TOK) * HD;
        for (int n = half; n < M_TOK; n += 2)
            acc += L[w * 144 + n] * vb[n * HD + d];
        if ((w & 1) == half)
            acc += L[576] * vb[M_TOK * HD + d];
    }
    red[tid] = acc;
    __syncthreads();
    if (half == 0) {
        float tot = tf32f((red[tid] + red[tid + 64]) * s_inv);
#pragma unroll
        for (int w = 0; w < 4; w++)
            g_opre[(size_t)((b * 4 + w) * N_TOK + M_TOK) * C_DIM + h * HD + d] = tot;
    }
}

// ---------------------------------------------------------------------------
extern "C" void kernel_launch(void* const* d_in, const int* in_sizes, int n_in,
                              void* d_out, int out_size)
{
    const float* x    = (const float*)d_in[0];
    const float* mask = (const float*)d_in[1];
    const float* rpb  = (const float*)d_in[2];
    const float* Wq   = (const float*)d_in[3];
    const float* bq   = (const float*)d_in[4];
    const float* Wk   = (const float*)d_in[5];
    const float* bk   = (const float*)d_in[6];
    const float* Wv   = (const float*)d_in[7];
    const float* bv   = (const float*)d_in[8];
    const float* Wo   = (const float*)d_in[9];
    const float* bo   = (const float*)d_in[10];
    float* out = (float*)d_out;

    cudaFuncSetAttribute(tgemm, cudaFuncAttributeMaxDynamicSharedMemorySize,
                         TGEMM_SMEM_BYTES);
    cudaFuncSetAttribute(attn_kernel, cudaFuncAttributeMaxDynamicSharedMemorySize,
                         AT_SMEM_BYTES);

    cvt_x_kernel<<<ROWS * C_DIM / 1024, 256>>>(x);
    cvt_w_kernel<<<dim3(C_DIM * C_DIM / 1024, 4), 256>>>(Wq, Wk, Wv, Wo);
    comb_kernel<<<dim3(N_TOK, NWIN * H_NUM), 160>>>(mask, rpb);

    // QKV: one launch, z selects the weight/output
    dim3 gqkv(4, 580, 3);   // 512/128 x 74240/128 x {Q,K,V}
    tgemm<<<gqkv, 256, TGEMM_SMEM_BYTES>>>(bq, bk, bv, nullptr, 0);

    attn_kernel<<<4096, 288, AT_SMEM_BYTES>>>();
    gx_kernel<<<1024, 128>>>(mask);

    dim3 go(4, 580, 1);
    tgemm<<<go, 256, TGEMM_SMEM_BYTES>>>(bo, nullptr, nullptr, out, 3);
}

// round 12
// speedup vs baseline: 1.7576x; 1.5685x over previous
#include <cuda_runtime.h>
#include <cuda_fp16.h>

// Problem constants
#define B_TOT 512
#define N_TOK 145
#define M_TOK 144
#define C_DIM 512
#define H_NUM 8
#define HD    64
#define NWIN  4
#define ROWS  (B_TOT * N_TOK)                   // 74240
#define QKV_ELEMS (B_TOT * H_NUM * N_TOK * HD)  // 38,010,880

// Scratch (device globals; no allocation allowed) — all fp16 now
__device__ __half g_q[QKV_ELEMS];
__device__ __half g_k[QKV_ELEMS];
__device__ __half g_v[QKV_ELEMS];
__device__ __half g_opre[ROWS * C_DIM];
__device__ __half g_xt[ROWS * C_DIM];           // f16-rounded x
__device__ __half g_wt[4][C_DIM * C_DIM];       // f16-rounded Wq,Wk,Wv,Wo
__device__ float  g_comb[NWIN * H_NUM][N_TOK * 152];  // mask+rpb, -inf pad

__device__ __forceinline__ unsigned pkh(float a, float b) {
    __half2 h = __floats2half2_rn(a, b);
    return reinterpret_cast<unsigned&>(h);
}

// ---------------------------------------------------------------------------
// Pre-conversion kernels (fp32 -> fp16 RN)
// ---------------------------------------------------------------------------
__global__ void cvt_x_kernel(const float* __restrict__ x) {
    int i = blockIdx.x * 256 + threadIdx.x;
    float4 v = ((const float4*)x)[i];
    uint2 o;
    o.x = pkh(v.x, v.y);
    o.y = pkh(v.z, v.w);
    ((uint2*)g_xt)[i] = o;
}

__global__ void cvt_w_kernel(const float* __restrict__ w0,
                             const float* __restrict__ w1,
                             const float* __restrict__ w2,
                             const float* __restrict__ w3) {
    const float* src = (blockIdx.y == 0) ? w0 : (blockIdx.y == 1) ? w1
                     : (blockIdx.y == 2) ? w2 : w3;
    int i = blockIdx.x * 256 + threadIdx.x;
    float4 v = ((const float4*)src)[i];
    uint2 o;
    o.x = pkh(v.x, v.y);
    o.y = pkh(v.z, v.w);
    ((uint2*)g_wt[blockIdx.y])[i] = o;
}

// Fused mask + rpb, stride 152, cols >=145 filled with -1e30 (auto-mask)
__global__ void comb_kernel(const float* __restrict__ mask,
                            const float* __restrict__ rpb) {
    int i = blockIdx.x, wh = blockIdx.y;
    int w = wh >> 3, h = wh & 7;
    int j = threadIdx.x;
    if (j >= 152) return;
    float v;
    if (j < N_TOK) {
        v = mask[(size_t)w * N_TOK * N_TOK + i * N_TOK + j];
        if (i < M_TOK && j < M_TOK) {
            int iH = i / 12, iW = i - iH * 12;
            int jH = j / 12, jW = j - jH * 12;
            int idx = (iH - jH + 11) * 23 + (iW - jW + 11);
            v += rpb[idx * H_NUM + h];
        }
    } else {
        v = -1e30f;
    }
    g_comb[wh][i * 152 + j] = v;
}

// ---------------------------------------------------------------------------
// Common mma helpers
// ---------------------------------------------------------------------------
__device__ __forceinline__ void cpasync16(unsigned saddr, const void* g) {
    asm volatile("cp.async.cg.shared.global [%0], [%1], 16;"
                 :: "r"(saddr), "l"(g) : "memory");
}

__device__ __forceinline__ void ldsm4(unsigned* r, unsigned addr) {
    asm volatile("ldmatrix.sync.aligned.m8n8.x4.shared.b16 {%0,%1,%2,%3}, [%4];"
                 : "=r"(r[0]), "=r"(r[1]), "=r"(r[2]), "=r"(r[3]) : "r"(addr));
}

__device__ __forceinline__ void ldsm4t(unsigned* r, unsigned addr) {
    asm volatile("ldmatrix.sync.aligned.m8n8.x4.trans.shared.b16 {%0,%1,%2,%3}, [%4];"
                 : "=r"(r[0]), "=r"(r[1]), "=r"(r[2]), "=r"(r[3]) : "r"(addr));
}

__device__ __forceinline__ void mma_f16(float* d,
    unsigned a0, unsigned a1, unsigned a2, unsigned a3,
    unsigned b0, unsigned b1)
{
    asm volatile(
        "mma.sync.aligned.m16n8k16.row.col.f32.f16.f16.f32 "
        "{%0,%1,%2,%3}, {%4,%5,%6,%7}, {%8,%9}, {%0,%1,%2,%3};"
        : "+f"(d[0]), "+f"(d[1]), "+f"(d[2]), "+f"(d[3])
        : "r"(a0), "r"(a1), "r"(a2), "r"(a3), "r"(b0), "r"(b1));
}

// ---------------------------------------------------------------------------
// FP16 tensor-core NT GEMM, cp.async 3-stage pipeline + ldmatrix.
// Block 128x128, 8 warps (2Mx4N), warp 64x32, mma.m16n8k16.
// smem per stage: A 128 rows x 128B (64 halves), B same; SW128 swizzle:
//   16B chunk q of row r stored at chunk (q ^ (r&7))   (conflict-free).
// qkv mode: gridDim.z = 3 (sel = blockIdx.z); mode 3 = final projection.
// ---------------------------------------------------------------------------
#define KCH 64              // k per stage (halves)
#define NSTG (C_DIM / KCH)  // 8
#define STG_BYTES 32768     // A 16KB + B 16KB
#define TGEMM_SMEM_BYTES (3 * STG_BYTES)   // 98304

__global__ void __launch_bounds__(256, 2) tgemm(
    const float* __restrict__ biasQ,
    const float* __restrict__ biasK,
    const float* __restrict__ biasV,
    float* __restrict__ outPlain,
    int mode)
{
    extern __shared__ char smd[];
    int sel = (mode == 3) ? 3 : (int)blockIdx.z;
    const __half* A = (sel == 3) ? g_opre : g_xt;
    const __half* W = g_wt[sel];
    const float* bias = (sel == 0) ? biasQ : (sel == 1) ? biasK
                      : (sel == 2) ? biasV : biasQ;

    int tid = threadIdx.x;
    int lane = tid & 31, warp = tid >> 5;
    int wm = warp & 1, wn = warp >> 1;
    int m0 = blockIdx.y * 128, n0 = blockIdx.x * 128;

    const __half* Ag = A + (size_t)m0 * C_DIM;
    const __half* Wg = W + (size_t)n0 * C_DIM;
    unsigned sbase = (unsigned)__cvta_generic_to_shared(smd);

    // cp.async mapping: 128 rows x 8 chunks = 1024 chunks per matrix; 4/thread
    unsigned soc[4]; const __half* gac[4]; const __half* gwc[4];
#pragma unroll
    for (int i = 0; i < 4; i++) {
        int c = tid + i * 256;
        int r = c >> 3, q = c & 7;
        soc[i] = (unsigned)(r * 128 + ((q ^ (r & 7)) << 4));
        gac[i] = Ag + (size_t)r * C_DIM + q * 8;
        gwc[i] = Wg + (size_t)r * C_DIM + q * 8;
    }

    float acc[4][4][4];
#pragma unroll
    for (int mt = 0; mt < 4; mt++)
#pragma unroll
        for (int nt = 0; nt < 4; nt++)
#pragma unroll
            for (int i = 0; i < 4; i++) acc[mt][nt][i] = 0.f;

    // Prologue: stages 0,1
#pragma unroll
    for (int s = 0; s < 2; s++) {
        unsigned sb = sbase + (unsigned)(s * STG_BYTES);
#pragma unroll
        for (int i = 0; i < 4; i++) {
            cpasync16(sb + soc[i], gac[i] + s * KCH);
            cpasync16(sb + 16384 + soc[i], gwc[i] + s * KCH);
        }
        asm volatile("cp.async.commit_group;");
    }

    int l15 = lane & 15, lh = lane >> 4;

    for (int s = 0; s < NSTG; s++) {
        if (s == NSTG - 1) asm volatile("cp.async.wait_group 0;");
        else               asm volatile("cp.async.wait_group 1;");
        __syncthreads();

        if (s + 2 < NSTG) {
            int sn = s + 2;
            unsigned sb = sbase + (unsigned)((sn % 3) * STG_BYTES);
#pragma unroll
            for (int i = 0; i < 4; i++) {
                cpasync16(sb + soc[i], gac[i] + sn * KCH);
                cpasync16(sb + 16384 + soc[i], gwc[i] + sn * KCH);
            }
            asm volatile("cp.async.commit_group;");
        }

        unsigned stw = sbase + (unsigned)((s % 3) * STG_BYTES);
#pragma unroll
        for (int ks = 0; ks < 4; ks++) {
            int q = 2 * ks + lh;
            unsigned af[4][4], bf[2][4];
#pragma unroll
            for (int mt = 0; mt < 4; mt++) {
                int row = wm * 64 + mt * 16 + l15;
                ldsm4(af[mt], stw + (unsigned)(row * 128 + ((q ^ (row & 7)) << 4)));
            }
#pragma unroll
            for (int p = 0; p < 2; p++) {
                int row = wn * 32 + p * 16 + l15;
                ldsm4(bf[p], stw + 16384u + (unsigned)(row * 128 + ((q ^ (row & 7)) << 4)));
            }
#pragma unroll
            for (int mt = 0; mt < 4; mt++)
#pragma unroll
                for (int n8 = 0; n8 < 4; n8++) {
                    int p = n8 >> 1;
                    unsigned b0 = (n8 & 1) ? bf[p][1] : bf[p][0];
                    unsigned b1 = (n8 & 1) ? bf[p][3] : bf[p][2];
                    mma_f16(acc[mt][n8], af[mt][0], af[mt][1], af[mt][2],
                            af[mt][3], b0, b1);
                }
        }
    }

    // Epilogue: bias add + scatter (half for QKV, float for final)
    __half* qkvbase = (sel == 0) ? g_q : (sel == 1) ? g_k : g_v;
    int cc = lane & 3, lrr = lane >> 2;
#pragma unroll
    for (int mt = 0; mt < 4; mt++) {
#pragma unroll
        for (int half_ = 0; half_ < 2; half_++) {
            int gm = m0 + wm * 64 + mt * 16 + lrr + half_ * 8;
            int b_ = gm / N_TOK;
            int t  = gm - b_ * N_TOK;
#pragma unroll
            for (int nt = 0; nt < 4; nt++) {
                int gn = n0 + wn * 32 + nt * 8 + cc * 2;
                float v0 = acc[mt][nt][half_ * 2 + 0] + bias[gn];
                float v1 = acc[mt][nt][half_ * 2 + 1] + bias[gn + 1];
                if (sel == 3) {
                    *(float2*)(outPlain + (size_t)gm * C_DIM + gn) =
                        make_float2(v0, v1);
                } else {
                    int h = gn >> 6, d = gn & 63;
                    __half* dst = qkvbase +
                        ((((size_t)b_ * H_NUM + h) * N_TOK + t) * HD + d);
                    *(unsigned*)dst = pkh(v0, v1);
                }
            }
        }
    }
}

// ---------------------------------------------------------------------------
// FP16 tensor-core window attention.  One block per (b_,h), 288 thr = 9 warps.
// Warp w owns rows [16w,16w+16).  K,V staged naturally [token][d] as halves
// (128B rows, SW128 swizzle).  QK: mma.m16n8k16, B via non-trans ldmatrix.
// PV: P packed from C-fragments straight into A-fragments (no shuffles);
// V as B operand via ldmatrix.trans.  Tokens padded to 160 (zeros).
// ---------------------------------------------------------------------------
#define AT_SMEM_BYTES (2 * 160 * 128)   // 40960

__global__ void __launch_bounds__(288) attn_kernel()
{
    extern __shared__ char sm[];
    char* Ks = sm;                // 160 x 128B
    char* Vs = sm + 160 * 128;    // 160 x 128B

    int bh = blockIdx.x;
    int b_ = bh >> 3, h = bh & 7, w = b_ & 3;
    const __half* gK = g_k + (size_t)bh * (N_TOK * HD);
    const __half* gV = g_v + (size_t)bh * (N_TOK * HD);
    const __half* gQ = g_q + (size_t)bh * (N_TOK * HD);
    const float* comb = g_comb[w * 8 + h];
    int tid = threadIdx.x, lane = tid & 31, warp = tid / 32;

    // Stage K and V: pure 16B copies, swizzled chunks, zero-pad rows >=145
    for (int i = tid; i < 160 * 8; i += 288) {
        int n = i >> 3, q = i & 7;
        uint4 kv = make_uint4(0, 0, 0, 0), vv = make_uint4(0, 0, 0, 0);
        if (n < N_TOK) {
            kv = *(const uint4*)(gK + n * 64 + q * 8);
            vv = *(const uint4*)(gV + n * 64 + q * 8);
        }
        int off = n * 128 + ((q ^ (n & 7)) << 4);
        *(uint4*)(Ks + off) = kv;
        *(uint4*)(Vs + off) = vv;
    }

    int c = lane & 3, lr = lane >> 2;
    int l15 = lane & 15, lh = lane >> 4;
    int m0 = warp * 16;

    // Q A-fragments straight from global (half pairs are the frag registers)
    unsigned aq[4][4];
    {
        const __half* q0 = gQ + (m0 + lr) * 64;
        const __half* q1 = gQ + (m0 + lr + 8) * 64;
#pragma unroll
        for (int ks = 0; ks < 4; ks++) {
            aq[ks][0] = *(const unsigned*)(q0 + 16 * ks + 2 * c);
            aq[ks][1] = *(const unsigned*)(q1 + 16 * ks + 2 * c);
            aq[ks][2] = *(const unsigned*)(q0 + 16 * ks + 2 * c + 8);
            aq[ks][3] = *(const unsigned*)(q1 + 16 * ks + 2 * c + 8);
        }
    }
    __syncthreads();

    unsigned ksBase = (unsigned)__cvta_generic_to_shared(Ks);
    unsigned vsBase = (unsigned)__cvta_generic_to_shared(Vs);

    float sacc[19][4];
#pragma unroll
    for (int t = 0; t < 19; t++)
#pragma unroll
        for (int i = 0; i < 4; i++) sacc[t][i] = 0.f;

    // ---- S = Q K^T ----  (4 k-steps of 16, 19 n-tiles)
#pragma unroll
    for (int ks = 0; ks < 4; ks++) {
        int q = 2 * ks + lh;
#pragma unroll
        for (int tp = 0; tp < 10; tp++) {
            int row = 16 * tp + l15;
            unsigned br[4];
            ldsm4(br, ksBase + (unsigned)(row * 128 + ((q ^ (row & 7)) << 4)));
            mma_f16(sacc[2 * tp], aq[ks][0], aq[ks][1], aq[ks][2], aq[ks][3],
                    br[0], br[2]);
            if (2 * tp + 1 < 19)
                mma_f16(sacc[2 * tp + 1], aq[ks][0], aq[ks][1], aq[ks][2],
                        aq[ks][3], br[1], br[3]);
        }
    }

    // ---- softmax in registers ----
    const float* crow0 = comb + (m0 + lr) * 152 + 2 * c;
    const float* crow1 = comb + (m0 + lr + 8) * 152 + 2 * c;
    float mx0 = -1e30f, mx1 = -1e30f;
#pragma unroll
    for (int t = 0; t < 19; t++) {
        float2 cb0 = *(const float2*)(crow0 + 8 * t);
        float2 cb1 = *(const float2*)(crow1 + 8 * t);
        sacc[t][0] = sacc[t][0] * 0.125f + cb0.x;
        sacc[t][1] = sacc[t][1] * 0.125f + cb0.y;
        sacc[t][2] = sacc[t][2] * 0.125f + cb1.x;
        sacc[t][3] = sacc[t][3] * 0.125f + cb1.y;
        mx0 = fmaxf(mx0, fmaxf(sacc[t][0], sacc[t][1]));
        mx1 = fmaxf(mx1, fmaxf(sacc[t][2], sacc[t][3]));
    }
    mx0 = fmaxf(mx0, __shfl_xor_sync(0xffffffffu, mx0, 1));
    mx0 = fmaxf(mx0, __shfl_xor_sync(0xffffffffu, mx0, 2));
    mx1 = fmaxf(mx1, __shfl_xor_sync(0xffffffffu, mx1, 1));
    mx1 = fmaxf(mx1, __shfl_xor_sync(0xffffffffu, mx1, 2));

    float l0 = 0.f, l1 = 0.f;
#pragma unroll
    for (int t = 0; t < 19; t++) {
        float p0 = __expf(sacc[t][0] - mx0);
        float p1 = __expf(sacc[t][1] - mx0);
        float p2 = __expf(sacc[t][2] - mx1);
        float p3 = __expf(sacc[t][3] - mx1);
        l0 += p0 + p1; l1 += p2 + p3;
        sacc[t][0] = p0; sacc[t][1] = p1; sacc[t][2] = p2; sacc[t][3] = p3;
    }
    l0 += __shfl_xor_sync(0xffffffffu, l0, 1);
    l0 += __shfl_xor_sync(0xffffffffu, l0, 2);
    l1 += __shfl_xor_sync(0xffffffffu, l1, 1);
    l1 += __shfl_xor_sync(0xffffffffu, l1, 2);

    // ---- O = P V ----  (10 k-steps of 16 tokens; P C-frag -> A-frag pack)
    float pacc[8][4];
#pragma unroll
    for (int dt = 0; dt < 8; dt++)
#pragma unroll
        for (int i = 0; i < 4; i++) pacc[dt][i] = 0.f;

#pragma unroll
    for (int kk = 0; kk < 10; kk++) {
        int t0 = 2 * kk, t1 = 2 * kk + 1;
        unsigned a0 = pkh(sacc[t0][0], sacc[t0][1]);
        unsigned a1 = pkh(sacc[t0][2], sacc[t0][3]);
        unsigned a2 = 0, a3 = 0;
        if (t1 < 19) {
            a2 = pkh(sacc[t1][0], sacc[t1][1]);
            a3 = pkh(sacc[t1][2], sacc[t1][3]);
        }
        int row = 16 * kk + l15;
        unsigned rowBase = vsBase + (unsigned)(row * 128);
        int r7 = row & 7;
#pragma unroll
        for (int vn = 0; vn < 4; vn++) {
            int q = 2 * vn + lh;
            unsigned br[4];
            ldsm4t(br, rowBase + (unsigned)((q ^ r7) << 4));
            mma_f16(pacc[2 * vn],     a0, a1, a2, a3, br[0], br[1]);
            mma_f16(pacc[2 * vn + 1], a0, a1, a2, a3, br[2], br[3]);
        }
    }

    float inv0 = 1.f / l0, inv1 = 1.f / l1;
    __half* dst0 = g_opre + (size_t)(b_ * N_TOK + m0 + lr) * C_DIM + h * HD;
    __half* dst1 = dst0 + 8 * C_DIM;
#pragma unroll
    for (int dt = 0; dt < 8; dt++) {
        *(unsigned*)(dst0 + dt * 8 + 2 * c) =
            pkh(pacc[dt][0] * inv0, pacc[dt][1] * inv0);
        *(unsigned*)(dst1 + dt * 8 + 2 * c) =
            pkh(pacc[dt][2] * inv1, pacc[dt][3] * inv1);
    }
}

// ---------------------------------------------------------------------------
// Global-token redistribution: one block per (b, h).  fp16 inputs, fp32 math.
// ---------------------------------------------------------------------------
__global__ void __launch_bounds__(128) gx_kernel(const float* __restrict__ mask)
{
    __shared__ __align__(16) float L[580];
    __shared__ __align__(16) float Qg[256];
    __shared__ __align__(16) float red[128];
    __shared__ float s_inv;

    int b = blockIdx.x >> 3, h = blockIdx.x & 7;
    int tid = threadIdx.x;

    for (int i = tid; i < 256; i += 128) {
        int w = i >> 6, d = i & 63;
        Qg[i] = __half2float(
            g_q[(((size_t)(b * 4 + w) * H_NUM + h) * N_TOK + M_TOK) * HD + d]);
    }
    __syncthreads();

    for (int idx = tid; idx < 577; idx += 128) {
        if (idx < 576) {
            int w = idx / 144, n = idx - w * 144;
            const __half2* kp = (const __half2*)(g_k +
                (((size_t)(b * 4 + w) * H_NUM + h) * N_TOK + n) * HD);
            const float* qp = Qg + w * 64;
            float dot = 0.f;
#pragma unroll
            for (int t = 0; t < 32; t++) {
                float2 kf = __half22float2(kp[t]);
                dot += kf.x * qp[2 * t] + kf.y * qp[2 * t + 1];
            }
            L[idx] = dot * 0.125f +
                     mask[(size_t)w * (N_TOK * N_TOK) + M_TOK * N_TOK + n];
        } else {
            float s = 0.f;
            for (int w = 0; w < 4; w++) {
                const __half2* kp = (const __half2*)(g_k +
                    (((size_t)(b * 4 + w) * H_NUM + h) * N_TOK + M_TOK) * HD);
                const float* qp = Qg + w * 64;
                float dot = 0.f;
#pragma unroll
                for (int t = 0; t < 32; t++) {
                    float2 kf = __half22float2(kp[t]);
                    dot += kf.x * qp[2 * t] + kf.y * qp[2 * t + 1];
                }
                s += dot * 0.125f +
                     mask[(size_t)w * (N_TOK * N_TOK) + M_TOK * N_TOK + M_TOK];
            }
            L[576] = s * 0.25f;
        }
    }
    __syncthreads();

    float mx = -1e30f;
    for (int idx = tid; idx < 577; idx += 128) mx = fmaxf(mx, L[idx]);
    red[tid] = mx;
    __syncthreads();
    for (int s2 = 64; s2 > 0; s2 >>= 1) {
        if (tid < s2) red[tid] = fmaxf(red[tid], red[tid + s2]);
        __syncthreads();
    }
    mx = red[0];
    __syncthreads();

    float ps = 0.f;
    for (int idx = tid; idx < 577; idx += 128) {
        float e = __expf(L[idx] - mx);
        L[idx] = e;
        ps += e;
    }
    red[tid] = ps;
    __syncthreads();
    for (int s2 = 64; s2 > 0; s2 >>= 1) {
        if (tid < s2) red[tid] += red[tid + s2];
        __syncthreads();
    }
    if (tid == 0) s_inv = 1.f / red[0];
    __syncthreads();

    int d = tid & 63, half_ = tid >> 6;
    float acc = 0.f;
    for (int w = 0; w < 4; w++) {
        const __half* vb = g_v + (((size_t)(b * 4 + w) * H_NUM + h) * N_TOK) * HD;
        for (int n = half_; n < M_TOK; n += 2)
            acc += L[w * 144 + n] * __half2float(vb[n * HD + d]);
        if ((w & 1) == half_)
            acc += L[576] * __half2float(vb[M_TOK * HD + d]);
    }
    red[tid] = acc;
    __syncthreads();
    if (half_ == 0) {
        __half tot = __float2half_rn((red[tid] + red[tid + 64]) * s_inv);
#pragma unroll
        for (int w = 0; w < 4; w++)
            g_opre[(size_t)((b * 4 + w) * N_TOK + M_TOK) * C_DIM + h * HD + d] = tot;
    }
}

// ---------------------------------------------------------------------------
extern "C" void kernel_launch(void* const* d_in, const int* in_sizes, int n_in,
                              void* d_out, int out_size)
{
    const float* x    = (const float*)d_in[0];
    const float* mask = (const float*)d_in[1];
    const float* rpb  = (const float*)d_in[2];
    const float* Wq   = (const float*)d_in[3];
    const float* bq   = (const float*)d_in[4];
    const float* Wk   = (const float*)d_in[5];
    const float* bk   = (const float*)d_in[6];
    const float* Wv   = (const float*)d_in[7];
    const float* bv   = (const float*)d_in[8];
    const float* Wo   = (const float*)d_in[9];
    const float* bo   = (const float*)d_in[10];
    float* out = (float*)d_out;

    cudaFuncSetAttribute(tgemm, cudaFuncAttributeMaxDynamicSharedMemorySize,
                         TGEMM_SMEM_BYTES);
    cudaFuncSetAttribute(attn_kernel, cudaFuncAttributeMaxDynamicSharedMemorySize,
                         AT_SMEM_BYTES);

    cvt_x_kernel<<<ROWS * C_DIM / 1024, 256>>>(x);
    cvt_w_kernel<<<dim3(C_DIM * C_DIM / 1024, 4), 256>>>(Wq, Wk, Wv, Wo);
    comb_kernel<<<dim3(N_TOK, NWIN * H_NUM), 160>>>(mask, rpb);

    // QKV: one launch, z selects the weight/output
    dim3 gqkv(4, 580, 3);
    tgemm<<<gqkv, 256, TGEMM_SMEM_BYTES>>>(bq, bk, bv, nullptr, 0);

    attn_kernel<<<4096, 288, AT_SMEM_BYTES>>>();
    gx_kernel<<<1024, 128>>>(mask);

    dim3 go(4, 580, 1);
    tgemm<<<go, 256, TGEMM_SMEM_BYTES>>>(bo, nullptr, nullptr, out, 3);
}

// round 16
// speedup vs baseline: 1.8888x; 1.0746x over previous
#include <cuda_runtime.h>
#include <cuda_fp16.h>

// Problem constants
#define B_TOT 512
#define N_TOK 145
#define M_TOK 144
#define C_DIM 512
#define H_NUM 8
#define HD    64
#define NWIN  4
#define ROWS  (B_TOT * N_TOK)                   // 74240
#define QKV_ELEMS (B_TOT * H_NUM * N_TOK * HD)  // 38,010,880

// Scratch (device globals; no allocation allowed) — all fp16
__device__ __half g_q[QKV_ELEMS];
__device__ __half g_k[QKV_ELEMS];
__device__ __half g_v[QKV_ELEMS];
__device__ __half g_opre[ROWS * C_DIM];
__device__ __half g_xt[ROWS * C_DIM];           // f16-rounded x
__device__ __half g_wt[4][C_DIM * C_DIM];       // f16-rounded Wq,Wk,Wv,Wo
__device__ float  g_comb[NWIN * H_NUM][N_TOK * 152];  // mask+rpb, -inf pad

__device__ __forceinline__ unsigned pkh(float a, float b) {
    __half2 h = __floats2half2_rn(a, b);
    return reinterpret_cast<unsigned&>(h);
}

// ---------------------------------------------------------------------------
// Merged pre-conversion: blocks [0, XB) convert x; [XB, XB+1024) convert W's
// ---------------------------------------------------------------------------
#define XB (ROWS * C_DIM / 1024)   // 37120

__global__ void cvt_all_kernel(const float* __restrict__ x,
                               const float* __restrict__ w0,
                               const float* __restrict__ w1,
                               const float* __restrict__ w2,
                               const float* __restrict__ w3) {
    int blk = blockIdx.x;
    if (blk < XB) {
        int i = blk * 256 + threadIdx.x;
        float4 v = ((const float4*)x)[i];
        uint2 o;
        o.x = pkh(v.x, v.y);
        o.y = pkh(v.z, v.w);
        ((uint2*)g_xt)[i] = o;
    } else {
        int wb = blk - XB;          // 0..1023
        int wi = wb >> 8;           // matrix 0..3
        const float* src = (wi == 0) ? w0 : (wi == 1) ? w1 : (wi == 2) ? w2 : w3;
        int i = (wb & 255) * 256 + threadIdx.x;
        float4 v = ((const float4*)src)[i];
        uint2 o;
        o.x = pkh(v.x, v.y);
        o.y = pkh(v.z, v.w);
        ((uint2*)g_wt[wi])[i] = o;
    }
}

// Fused mask + rpb, stride 152, cols >=145 filled with -1e30 (auto-mask)
__global__ void comb_kernel(const float* __restrict__ mask,
                            const float* __restrict__ rpb) {
    int i = blockIdx.x, wh = blockIdx.y;
    int w = wh >> 3, h = wh & 7;
    int j = threadIdx.x;
    if (j >= 152) return;
    float v;
    if (j < N_TOK) {
        v = mask[(size_t)w * N_TOK * N_TOK + i * N_TOK + j];
        if (i < M_TOK && j < M_TOK) {
            int iH = i / 12, iW = i - iH * 12;
            int jH = j / 12, jW = j - jH * 12;
            int idx = (iH - jH + 11) * 23 + (iW - jW + 11);
            v += rpb[idx * H_NUM + h];
        }
    } else {
        v = -1e30f;
    }
    g_comb[wh][i * 152 + j] = v;
}

// ---------------------------------------------------------------------------
// Common helpers
// ---------------------------------------------------------------------------
__device__ __forceinline__ void cpasync16(unsigned saddr, const void* g) {
    asm volatile("cp.async.cg.shared.global [%0], [%1], 16;"
                 :: "r"(saddr), "l"(g) : "memory");
}

__device__ __forceinline__ void ldsm4(unsigned* r, unsigned addr) {
    asm volatile("ldmatrix.sync.aligned.m8n8.x4.shared.b16 {%0,%1,%2,%3}, [%4];"
                 : "=r"(r[0]), "=r"(r[1]), "=r"(r[2]), "=r"(r[3]) : "r"(addr));
}

__device__ __forceinline__ void ldsm4t(unsigned* r, unsigned addr) {
    asm volatile("ldmatrix.sync.aligned.m8n8.x4.trans.shared.b16 {%0,%1,%2,%3}, [%4];"
                 : "=r"(r[0]), "=r"(r[1]), "=r"(r[2]), "=r"(r[3]) : "r"(addr));
}

__device__ __forceinline__ void mma_f16(float* d,
    unsigned a0, unsigned a1, unsigned a2, unsigned a3,
    unsigned b0, unsigned b1)
{
    asm volatile(
        "mma.sync.aligned.m16n8k16.row.col.f32.f16.f16.f32 "
        "{%0,%1,%2,%3}, {%4,%5,%6,%7}, {%8,%9}, {%0,%1,%2,%3};"
        : "+f"(d[0]), "+f"(d[1]), "+f"(d[2]), "+f"(d[3])
        : "r"(a0), "r"(a1), "r"(a2), "r"(a3), "r"(b0), "r"(b1));
}

// ---------------------------------------------------------------------------
// FP16 tensor-core NT GEMM (R12-proven, unchanged).
// ---------------------------------------------------------------------------
#define KCH 64              // k per stage (halves)
#define NSTG (C_DIM / KCH)  // 8
#define STG_BYTES 32768     // A 16KB + B 16KB
#define TGEMM_SMEM_BYTES (3 * STG_BYTES)   // 98304

__global__ void __launch_bounds__(256, 2) tgemm(
    const float* __restrict__ biasQ,
    const float* __restrict__ biasK,
    const float* __restrict__ biasV,
    float* __restrict__ outPlain,
    int mode)
{
    extern __shared__ char smd[];
    int sel = (mode == 3) ? 3 : (int)blockIdx.z;
    const __half* A = (sel == 3) ? g_opre : g_xt;
    const __half* W = g_wt[sel];
    const float* bias = (sel == 0) ? biasQ : (sel == 1) ? biasK
                      : (sel == 2) ? biasV : biasQ;

    int tid = threadIdx.x;
    int lane = tid & 31, warp = tid >> 5;
    int wm = warp & 1, wn = warp >> 1;
    int m0 = blockIdx.y * 128, n0 = blockIdx.x * 128;

    const __half* Ag = A + (size_t)m0 * C_DIM;
    const __half* Wg = W + (size_t)n0 * C_DIM;
    unsigned sbase = (unsigned)__cvta_generic_to_shared(smd);

    unsigned soc[4]; const __half* gac[4]; const __half* gwc[4];
#pragma unroll
    for (int i = 0; i < 4; i++) {
        int c = tid + i * 256;
        int r = c >> 3, q = c & 7;
        soc[i] = (unsigned)(r * 128 + ((q ^ (r & 7)) << 4));
        gac[i] = Ag + (size_t)r * C_DIM + q * 8;
        gwc[i] = Wg + (size_t)r * C_DIM + q * 8;
    }

    float acc[4][4][4];
#pragma unroll
    for (int mt = 0; mt < 4; mt++)
#pragma unroll
        for (int nt = 0; nt < 4; nt++)
#pragma unroll
            for (int i = 0; i < 4; i++) acc[mt][nt][i] = 0.f;

#pragma unroll
    for (int s = 0; s < 2; s++) {
        unsigned sb = sbase + (unsigned)(s * STG_BYTES);
#pragma unroll
        for (int i = 0; i < 4; i++) {
            cpasync16(sb + soc[i], gac[i] + s * KCH);
            cpasync16(sb + 16384 + soc[i], gwc[i] + s * KCH);
        }
        asm volatile("cp.async.commit_group;");
    }

    int l15 = lane & 15, lh = lane >> 4;

    for (int s = 0; s < NSTG; s++) {
        if (s == NSTG - 1) asm volatile("cp.async.wait_group 0;");
        else               asm volatile("cp.async.wait_group 1;");
        __syncthreads();

        if (s + 2 < NSTG) {
            int sn = s + 2;
            unsigned sb = sbase + (unsigned)((sn % 3) * STG_BYTES);
#pragma unroll
            for (int i = 0; i < 4; i++) {
                cpasync16(sb + soc[i], gac[i] + sn * KCH);
                cpasync16(sb + 16384 + soc[i], gwc[i] + sn * KCH);
            }
            asm volatile("cp.async.commit_group;");
        }

        unsigned stw = sbase + (unsigned)((s % 3) * STG_BYTES);
#pragma unroll
        for (int ks = 0; ks < 4; ks++) {
            int q = 2 * ks + lh;
            unsigned af[4][4], bf[2][4];
#pragma unroll
            for (int mt = 0; mt < 4; mt++) {
                int row = wm * 64 + mt * 16 + l15;
                ldsm4(af[mt], stw + (unsigned)(row * 128 + ((q ^ (row & 7)) << 4)));
            }
#pragma unroll
            for (int p = 0; p < 2; p++) {
                int row = wn * 32 + p * 16 + l15;
                ldsm4(bf[p], stw + 16384u + (unsigned)(row * 128 + ((q ^ (row & 7)) << 4)));
            }
#pragma unroll
            for (int mt = 0; mt < 4; mt++)
#pragma unroll
                for (int n8 = 0; n8 < 4; n8++) {
                    int p = n8 >> 1;
                    unsigned b0 = (n8 & 1) ? bf[p][1] : bf[p][0];
                    unsigned b1 = (n8 & 1) ? bf[p][3] : bf[p][2];
                    mma_f16(acc[mt][n8], af[mt][0], af[mt][1], af[mt][2],
                            af[mt][3], b0, b1);
                }
        }
    }

    __half* qkvbase = (sel == 0) ? g_q : (sel == 1) ? g_k : g_v;
    int cc = lane & 3, lrr = lane >> 2;
#pragma unroll
    for (int mt = 0; mt < 4; mt++) {
#pragma unroll
        for (int half_ = 0; half_ < 2; half_++) {
            int gm = m0 + wm * 64 + mt * 16 + lrr + half_ * 8;
            int b_ = gm / N_TOK;
            int t  = gm - b_ * N_TOK;
#pragma unroll
            for (int nt = 0; nt < 4; nt++) {
                int gn = n0 + wn * 32 + nt * 8 + cc * 2;
                float v0 = acc[mt][nt][half_ * 2 + 0] + bias[gn];
                float v1 = acc[mt][nt][half_ * 2 + 1] + bias[gn + 1];
                if (sel == 3) {
                    *(float2*)(outPlain + (size_t)gm * C_DIM + gn) =
                        make_float2(v0, v1);
                } else {
                    int h = gn >> 6, d = gn & 63;
                    __half* dst = qkvbase +
                        ((((size_t)b_ * H_NUM + h) * N_TOK + t) * HD + d);
                    *(unsigned*)dst = pkh(v0, v1);
                }
            }
        }
    }
}

// ---------------------------------------------------------------------------
// Merged attention + gx launch: blocks [0,4096) = window attention,
// blocks [4096,5120) = global-token redistribution (independent of attn).
// ---------------------------------------------------------------------------
#define AT_SMEM_BYTES (2 * 160 * 128)   // 40960
#define ATTN_BLOCKS 4096

__device__ __forceinline__ void attn_block(int bh, int tid, char* sm)
{
    char* Ks = sm;                // 160 x 128B
    char* Vs = sm + 160 * 128;    // 160 x 128B

    int b_ = bh >> 3, h = bh & 7, w = b_ & 3;
    const __half* gK = g_k + (size_t)bh * (N_TOK * HD);
    const __half* gV = g_v + (size_t)bh * (N_TOK * HD);
    const __half* gQ = g_q + (size_t)bh * (N_TOK * HD);
    const float* comb = g_comb[w * 8 + h];
    int lane = tid & 31, warp = tid / 32;

    unsigned ksBase = (unsigned)__cvta_generic_to_shared(Ks);
    unsigned vsBase = (unsigned)__cvta_generic_to_shared(Vs);

    // Zero-pad rows 145..159 (15 rows x 8 chunks x 2 matrices = 240 uint4)
    for (int i = tid; i < 240; i += 288) {
        int m = i >= 120;                 // 0=K, 1=V
        int r = i - m * 120;
        int n = 145 + (r >> 3), q = r & 7;
        int off = n * 128 + ((q ^ (n & 7)) << 4);
        *(uint4*)((m ? Vs : Ks) + off) = make_uint4(0, 0, 0, 0);
    }
    // cp.async stage K and V rows 0..144 (1160 chunks each)
    for (int i = tid; i < 2 * N_TOK * 8; i += 288) {
        int m = i >= N_TOK * 8;
        int r = i - m * (N_TOK * 8);
        int n = r >> 3, q = r & 7;
        unsigned off = (unsigned)(n * 128 + ((q ^ (n & 7)) << 4));
        const __half* src = (m ? gV : gK) + n * 64 + q * 8;
        cpasync16((m ? vsBase : ksBase) + off, src);
    }
    asm volatile("cp.async.commit_group;");

    int c = lane & 3, lr = lane >> 2;
    int l15 = lane & 15, lh = lane >> 4;
    int m0 = warp * 16;

    // Q A-fragments from global — overlaps with cp.async staging
    unsigned aq[4][4];
    {
        const __half* q0 = gQ + (m0 + lr) * 64;
        const __half* q1 = gQ + (m0 + lr + 8) * 64;
#pragma unroll
        for (int ks = 0; ks < 4; ks++) {
            aq[ks][0] = *(const unsigned*)(q0 + 16 * ks + 2 * c);
            aq[ks][1] = *(const unsigned*)(q1 + 16 * ks + 2 * c);
            aq[ks][2] = *(const unsigned*)(q0 + 16 * ks + 2 * c + 8);
            aq[ks][3] = *(const unsigned*)(q1 + 16 * ks + 2 * c + 8);
        }
    }
    asm volatile("cp.async.wait_group 0;");
    __syncthreads();

    float sacc[19][4];
#pragma unroll
    for (int t = 0; t < 19; t++)
#pragma unroll
        for (int i = 0; i < 4; i++) sacc[t][i] = 0.f;

    // ---- S = Q K^T ----
#pragma unroll
    for (int ks = 0; ks < 4; ks++) {
        int q = 2 * ks + lh;
#pragma unroll
        for (int tp = 0; tp < 10; tp++) {
            int row = 16 * tp + l15;
            unsigned br[4];
            ldsm4(br, ksBase + (unsigned)(row * 128 + ((q ^ (row & 7)) << 4)));
            mma_f16(sacc[2 * tp], aq[ks][0], aq[ks][1], aq[ks][2], aq[ks][3],
                    br[0], br[2]);
            if (2 * tp + 1 < 19)
                mma_f16(sacc[2 * tp + 1], aq[ks][0], aq[ks][1], aq[ks][2],
                        aq[ks][3], br[1], br[3]);
        }
    }

    // ---- softmax in registers ----
    const float* crow0 = comb + (m0 + lr) * 152 + 2 * c;
    const float* crow1 = comb + (m0 + lr + 8) * 152 + 2 * c;
    float mx0 = -1e30f, mx1 = -1e30f;
#pragma unroll
    for (int t = 0; t < 19; t++) {
        float2 cb0 = *(const float2*)(crow0 + 8 * t);
        float2 cb1 = *(const float2*)(crow1 + 8 * t);
        sacc[t][0] = sacc[t][0] * 0.125f + cb0.x;
        sacc[t][1] = sacc[t][1] * 0.125f + cb0.y;
        sacc[t][2] = sacc[t][2] * 0.125f + cb1.x;
        sacc[t][3] = sacc[t][3] * 0.125f + cb1.y;
        mx0 = fmaxf(mx0, fmaxf(sacc[t][0], sacc[t][1]));
        mx1 = fmaxf(mx1, fmaxf(sacc[t][2], sacc[t][3]));
    }
    mx0 = fmaxf(mx0, __shfl_xor_sync(0xffffffffu, mx0, 1));
    mx0 = fmaxf(mx0, __shfl_xor_sync(0xffffffffu, mx0, 2));
    mx1 = fmaxf(mx1, __shfl_xor_sync(0xffffffffu, mx1, 1));
    mx1 = fmaxf(mx1, __shfl_xor_sync(0xffffffffu, mx1, 2));

    float l0 = 0.f, l1 = 0.f;
#pragma unroll
    for (int t = 0; t < 19; t++) {
        float p0 = __expf(sacc[t][0] - mx0);
        float p1 = __expf(sacc[t][1] - mx0);
        float p2 = __expf(sacc[t][2] - mx1);
        float p3 = __expf(sacc[t][3] - mx1);
        l0 += p0 + p1; l1 += p2 + p3;
        sacc[t][0] = p0; sacc[t][1] = p1; sacc[t][2] = p2; sacc[t][3] = p3;
    }
    l0 += __shfl_xor_sync(0xffffffffu, l0, 1);
    l0 += __shfl_xor_sync(0xffffffffu, l0, 2);
    l1 += __shfl_xor_sync(0xffffffffu, l1, 1);
    l1 += __shfl_xor_sync(0xffffffffu, l1, 2);

    // ---- O = P V ----
    float pacc[8][4];
#pragma unroll
    for (int dt = 0; dt < 8; dt++)
#pragma unroll
        for (int i = 0; i < 4; i++) pacc[dt][i] = 0.f;

#pragma unroll
    for (int kk = 0; kk < 10; kk++) {
        int t0 = 2 * kk, t1 = 2 * kk + 1;
        unsigned a0 = pkh(sacc[t0][0], sacc[t0][1]);
        unsigned a1 = pkh(sacc[t0][2], sacc[t0][3]);
        unsigned a2 = 0, a3 = 0;
        if (t1 < 19) {
            a2 = pkh(sacc[t1][0], sacc[t1][1]);
            a3 = pkh(sacc[t1][2], sacc[t1][3]);
        }
        int row = 16 * kk + l15;
        unsigned rowBase = vsBase + (unsigned)(row * 128);
        int r7 = row & 7;
#pragma unroll
        for (int vn = 0; vn < 4; vn++) {
            int q = 2 * vn + lh;
            unsigned br[4];
            ldsm4t(br, rowBase + (unsigned)((q ^ r7) << 4));
            mma_f16(pacc[2 * vn],     a0, a1, a2, a3, br[0], br[1]);
            mma_f16(pacc[2 * vn + 1], a0, a1, a2, a3, br[2], br[3]);
        }
    }

    float inv0 = 1.f / l0, inv1 = 1.f / l1;
    __half* dst0 = g_opre + (size_t)(b_ * N_TOK + m0 + lr) * C_DIM + h * HD;
    __half* dst1 = dst0 + 8 * C_DIM;
#pragma unroll
    for (int dt = 0; dt < 8; dt++) {
        *(unsigned*)(dst0 + dt * 8 + 2 * c) =
            pkh(pacc[dt][0] * inv0, pacc[dt][1] * inv0);
        *(unsigned*)(dst1 + dt * 8 + 2 * c) =
            pkh(pacc[dt][2] * inv1, pacc[dt][3] * inv1);
    }
}

// gx block, restructured for 288 threads (threads >=128 idle through syncs)
__device__ __forceinline__ void gx_block(int gb, int tid, char* sm,
                                         const float* __restrict__ mask)
{
    float* L   = (float*)sm;                 // 580 floats
    float* Qg  = L + 580;                    // 256
    float* red = Qg + 256;                   // 128
    float* s_inv = red + 128;                // 1

    int b = gb >> 3, h = gb & 7;

    if (tid < 256) {
        int w = tid >> 6, d = tid & 63;
        Qg[tid] = __half2float(
            g_q[(((size_t)(b * 4 + w) * H_NUM + h) * N_TOK + M_TOK) * HD + d]);
    }
    __syncthreads();

    for (int idx = tid; idx < 577; idx += 288) {
        if (idx < 576) {
            int w = idx / 144, n = idx - w * 144;
            const __half2* kp = (const __half2*)(g_k +
                (((size_t)(b * 4 + w) * H_NUM + h) * N_TOK + n) * HD);
            const float* qp = Qg + w * 64;
            float dot = 0.f;
#pragma unroll
            for (int t = 0; t < 32; t++) {
                float2 kf = __half22float2(kp[t]);
                dot += kf.x * qp[2 * t] + kf.y * qp[2 * t + 1];
            }
            L[idx] = dot * 0.125f +
                     mask[(size_t)w * (N_TOK * N_TOK) + M_TOK * N_TOK + n];
        } else {
            float s = 0.f;
            for (int w = 0; w < 4; w++) {
                const __half2* kp = (const __half2*)(g_k +
                    (((size_t)(b * 4 + w) * H_NUM + h) * N_TOK + M_TOK) * HD);
                const float* qp = Qg + w * 64;
                float dot = 0.f;
#pragma unroll
                for (int t = 0; t < 32; t++) {
                    float2 kf = __half22float2(kp[t]);
                    dot += kf.x * qp[2 * t] + kf.y * qp[2 * t + 1];
                }
                s += dot * 0.125f +
                     mask[(size_t)w * (N_TOK * N_TOK) + M_TOK * N_TOK + M_TOK];
            }
            L[576] = s * 0.25f;
        }
    }
    __syncthreads();

    if (tid < 128) {
        float mx = -1e30f;
        for (int idx = tid; idx < 577; idx += 128) mx = fmaxf(mx, L[idx]);
        red[tid] = mx;
    }
    __syncthreads();
    for (int s2 = 64; s2 > 0; s2 >>= 1) {
        if (tid < s2) red[tid] = fmaxf(red[tid], red[tid + s2]);
        __syncthreads();
    }
    float mx = red[0];
    __syncthreads();

    if (tid < 128) {
        float ps = 0.f;
        for (int idx = tid; idx < 577; idx += 128) {
            float e = __expf(L[idx] - mx);
            L[idx] = e;
            ps += e;
        }
        red[tid] = ps;
    }
    __syncthreads();
    for (int s2 = 64; s2 > 0; s2 >>= 1) {
        if (tid < s2) red[tid] += red[tid + s2];
        __syncthreads();
    }
    if (tid == 0) *s_inv = 1.f / red[0];
    __syncthreads();

    if (tid < 128) {
        int d = tid & 63, half_ = tid >> 6;
        float acc = 0.f;
        for (int w = 0; w < 4; w++) {
            const __half* vb = g_v +
                (((size_t)(b * 4 + w) * H_NUM + h) * N_TOK) * HD;
            for (int n = half_; n < M_TOK; n += 2)
                acc += L[w * 144 + n] * __half2float(vb[n * HD + d]);
            if ((w & 1) == half_)
                acc += L[576] * __half2float(vb[M_TOK * HD + d]);
        }
        red[tid] = acc;
    }
    __syncthreads();
    if (tid < 64) {
        __half tot = __float2half_rn((red[tid] + red[tid + 64]) * (*s_inv));
#pragma unroll
        for (int w = 0; w < 4; w++)
            g_opre[(size_t)((b * 4 + w) * N_TOK + M_TOK) * C_DIM + tid +
                   h * HD] = tot;
    }
}

__global__ void __launch_bounds__(288) attn_gx_kernel(
    const float* __restrict__ mask)
{
    extern __shared__ char sm[];
    int tid = threadIdx.x;
    if (blockIdx.x < ATTN_BLOCKS)
        attn_block(blockIdx.x, tid, sm);
    else
        gx_block(blockIdx.x - ATTN_BLOCKS, tid, sm, mask);
}

// ---------------------------------------------------------------------------
extern "C" void kernel_launch(void* const* d_in, const int* in_sizes, int n_in,
                              void* d_out, int out_size)
{
    const float* x    = (const float*)d_in[0];
    const float* mask = (const float*)d_in[1];
    const float* rpb  = (const float*)d_in[2];
    const float* Wq   = (const float*)d_in[3];
    const float* bq   = (const float*)d_in[4];
    const float* Wk   = (const float*)d_in[5];
    const float* bk   = (const float*)d_in[6];
    const float* Wv   = (const float*)d_in[7];
    const float* bv   = (const float*)d_in[8];
    const float* Wo   = (const float*)d_in[9];
    const float* bo   = (const float*)d_in[10];
    float* out = (float*)d_out;

    cudaFuncSetAttribute(tgemm, cudaFuncAttributeMaxDynamicSharedMemorySize,
                         TGEMM_SMEM_BYTES);
    cudaFuncSetAttribute(attn_gx_kernel,
                         cudaFuncAttributeMaxDynamicSharedMemorySize,
                         AT_SMEM_BYTES);

    cvt_all_kernel<<<XB + 1024, 256>>>(x, Wq, Wk, Wv, Wo);
    comb_kernel<<<dim3(N_TOK, NWIN * H_NUM), 160>>>(mask, rpb);

    dim3 gqkv(4, 580, 3);
    tgemm<<<gqkv, 256, TGEMM_SMEM_BYTES>>>(bq, bk, bv, nullptr, 0);

    attn_gx_kernel<<<ATTN_BLOCKS + B_TOT / NWIN * H_NUM, 288,
                     AT_SMEM_BYTES>>>(mask);

    dim3 go(4, 580, 1);
    tgemm<<<go, 256, TGEMM_SMEM_BYTES>>>(bo, nullptr, nullptr, out, 3);
}